// round 14
// baseline (speedup 1.0000x reference)
#include <cuda_runtime.h>
#include <cuda_bf16.h>
#include <cstdint>
#include <math.h>

#define BB 2
#define HH 16
#define SS 2048
#define HD 128
#define DD 2048
#define KKEEP 819
#define NEGV -1e9f
#define FULLW 0xffffffffu

// ---------------- scratch (device globals; no allocation allowed) ----------
__device__ __nv_bfloat16 g_qhi [BB*HH*SS*HD];  // [bh][s][d]
__device__ __nv_bfloat16 g_qlo [BB*HH*SS*HD];
__device__ __nv_bfloat16 g_khi [BB*HH*SS*HD];  // [bh][t][d]
__device__ __nv_bfloat16 g_klo [BB*HH*SS*HD];
__device__ __nv_bfloat16 g_vthi[BB*HH*HD*SS];  // [bh][d][t]
__device__ __nv_bfloat16 g_vtlo[BB*HH*HD*SS];

__device__ __nv_bfloat16 g_xhi[(size_t)BB*SS*DD];   // x split [b][s][D]
__device__ __nv_bfloat16 g_xlo[(size_t)BB*SS*DD];
__device__ __nv_bfloat16 g_wwhi[3*HH*HD*HD];        // Wq/Wk/Wv split [w][h][e][k]
__device__ __nv_bfloat16 g_wwlo[3*HH*HD*HD];

__device__ float         g_sc [(size_t)BB*HH*SS*SS];   // scores [bh][s][t]
__device__ __nv_bfloat16 g_wh [(size_t)BB*HH*SS*SS];   // UNNORMALIZED weights hi
__device__ __nv_bfloat16 g_wl [(size_t)BB*HH*SS*SS];   // UNNORMALIZED weights lo
__device__ float         g_rsv[(size_t)BB*HH*SS];      // per-row 1/sum

// proj operands (A written directly by av_gemm epilogue)
__device__ __nv_bfloat16 g_Ahi[(size_t)BB*DD*SS];      // [b][i][s]
__device__ __nv_bfloat16 g_Alo[(size_t)BB*DD*SS];
__device__ __nv_bfloat16 g_Whi[(size_t)DD*SS];
__device__ __nv_bfloat16 g_Wlo[(size_t)DD*SS];

// ---------------- common helpers -------------------------------------------
__device__ __forceinline__ uint32_t smem_u32(const void* p) {
    uint32_t a;
    asm("{ .reg .u64 t; cvta.to.shared.u64 t, %1; cvt.u32.u64 %0, t; }" : "=r"(a) : "l"(p));
    return a;
}
__device__ __forceinline__ void cpa16(uint32_t s, const void* g) {
    asm volatile("cp.async.cg.shared.global [%0], [%1], 16;" :: "r"(s), "l"(g));
}
__device__ __forceinline__ void ldsm4(uint32_t* r, uint32_t a) {
    asm volatile("ldmatrix.sync.aligned.m8n8.x4.shared.b16 {%0,%1,%2,%3}, [%4];"
                 : "=r"(r[0]), "=r"(r[1]), "=r"(r[2]), "=r"(r[3]) : "r"(a));
}
__device__ __forceinline__ void mma16816(float* c, const uint32_t* a, uint32_t b0, uint32_t b1) {
    asm volatile("mma.sync.aligned.m16n8k16.row.col.f32.bf16.bf16.f32 "
                 "{%0,%1,%2,%3}, {%4,%5,%6,%7}, {%8,%9}, {%0,%1,%2,%3};"
                 : "+f"(c[0]), "+f"(c[1]), "+f"(c[2]), "+f"(c[3])
                 : "r"(a[0]), "r"(a[1]), "r"(a[2]), "r"(a[3]), "r"(b0), "r"(b1));
}
__device__ __forceinline__ void splitbf(float a, __nv_bfloat16& h, __nv_bfloat16& l) {
    h = __float2bfloat16(a);
    l = __float2bfloat16(a - __bfloat162float(h));
}
__device__ __forceinline__ unsigned pack2(__nv_bfloat16 a, __nv_bfloat16 b) {
    return (unsigned)*(unsigned short*)&a | ((unsigned)*(unsigned short*)&b << 16);
}

// ---------------------------------------------------------------------------
// gemm3 compute step on one 64-K chunk staged at sa (4 x 16KB buffers)
// ---------------------------------------------------------------------------
__device__ __forceinline__ void gemm3_compute(
    float (*acc)[8][4], uint32_t sa,
    int rowa_l, int ca_l, int rowb_l, int cb_l)
{
    #pragma unroll
    for (int kstep = 0; kstep < 4; kstep++) {
        uint32_t ah[2][4], al[2][4];
        #pragma unroll
        for (int i = 0; i < 2; i++) {
            int row = rowa_l + i*16;
            int c16 = kstep*2 + ca_l;
            uint32_t off = (uint32_t)row*128 + 16u*(uint32_t)(c16 ^ (row & 7));
            ldsm4(ah[i], sa + off);
            ldsm4(al[i], sa + 16384 + off);
        }
        #pragma unroll
        for (int j4 = 0; j4 < 4; j4++) {
            int row = rowb_l + j4*16;
            int c16 = kstep*2 + cb_l;
            uint32_t off = (uint32_t)row*128 + 16u*(uint32_t)(c16 ^ (row & 7));
            uint32_t bhf[4], blf[4];
            ldsm4(bhf, sa + 32768 + off);
            ldsm4(blf, sa + 49152 + off);
            #pragma unroll
            for (int i = 0; i < 2; i++) {
                mma16816(acc[i][2*j4+0], ah[i], bhf[0], bhf[1]);
                mma16816(acc[i][2*j4+1], ah[i], bhf[2], bhf[3]);
                mma16816(acc[i][2*j4+0], al[i], bhf[0], bhf[1]);
                mma16816(acc[i][2*j4+1], al[i], bhf[2], bhf[3]);
                mma16816(acc[i][2*j4+0], ah[i], blf[0], blf[1]);
                mma16816(acc[i][2*j4+1], ah[i], blf[2], blf[3]);
            }
        }
    }
}

// ---------------------------------------------------------------------------
// Single-stage gemm3 (64KB smem) — for short K; occupancy 3 CTA/SM
// ---------------------------------------------------------------------------
#define G1_SMEM 65536

__device__ __forceinline__ void gemm3_1s(
    float (*acc)[8][4], uint32_t sb, int tid,
    const __nv_bfloat16* Ah, const __nv_bfloat16* Al, size_t strideA,
    const __nv_bfloat16* Bh, const __nv_bfloat16* Bl, size_t strideB,
    int NC)
{
    int lane = tid & 31, wid = tid >> 5;
    int wm = wid & 3, wn = wid >> 2;
    int lrow = tid >> 3, lc16 = tid & 7;

    int rowa_l = wm*32 + (lane & 15);
    int ca_l   = (lane >> 4);
    int rowb_l = wn*64 + (lane & 7) + ((lane >> 4) << 3);
    int cb_l   = (lane >> 3) & 1;

    for (int c = 0; c < NC; c++) {
        int kk = c * 64;
        #pragma unroll
        for (int rep = 0; rep < 4; rep++) {
            int row = lrow + rep*32;
            uint32_t off = (uint32_t)row*128 + 16u*(uint32_t)(lc16 ^ (row & 7));
            cpa16(sb +     0 + off, Ah + (size_t)row*strideA + kk + lc16*8);
            cpa16(sb + 16384 + off, Al + (size_t)row*strideA + kk + lc16*8);
            cpa16(sb + 32768 + off, Bh + (size_t)row*strideB + kk + lc16*8);
            cpa16(sb + 49152 + off, Bl + (size_t)row*strideB + kk + lc16*8);
        }
        asm volatile("cp.async.commit_group;");
        asm volatile("cp.async.wait_group 0;");
        __syncthreads();
        gemm3_compute(acc, sb, rowa_l, ca_l, rowb_l, cb_l);
        __syncthreads();
    }
}

// ---------------------------------------------------------------------------
// Double-buffered gemm3 (128KB smem) — for long K (av_gemm)
// ---------------------------------------------------------------------------
#define G3_STAGE 65536
#define G3_SMEM  (2*G3_STAGE)

__device__ __forceinline__ void gemm3_core(
    float (*acc)[8][4], uint32_t sb, int tid,
    const __nv_bfloat16* Ah, const __nv_bfloat16* Al, size_t strideA,
    const __nv_bfloat16* Bh, const __nv_bfloat16* Bl, size_t strideB,
    int NC)
{
    int lane = tid & 31, wid = tid >> 5;
    int wm = wid & 3, wn = wid >> 2;
    int lrow = tid >> 3, lc16 = tid & 7;

    int rowa_l = wm*32 + (lane & 15);
    int ca_l   = (lane >> 4);
    int rowb_l = wn*64 + (lane & 7) + ((lane >> 4) << 3);
    int cb_l   = (lane >> 3) & 1;

    {
        uint32_t sa = sb;
        #pragma unroll
        for (int rep = 0; rep < 4; rep++) {
            int row = lrow + rep*32;
            uint32_t off = (uint32_t)row*128 + 16u*(uint32_t)(lc16 ^ (row & 7));
            cpa16(sa +     0 + off, Ah + (size_t)row*strideA + lc16*8);
            cpa16(sa + 16384 + off, Al + (size_t)row*strideA + lc16*8);
            cpa16(sa + 32768 + off, Bh + (size_t)row*strideB + lc16*8);
            cpa16(sa + 49152 + off, Bl + (size_t)row*strideB + lc16*8);
        }
        asm volatile("cp.async.commit_group;");
    }

    for (int c = 0; c < NC; c++) {
        int st = c & 1;
        if (c + 1 < NC) {
            int kk = (c + 1) * 64;
            uint32_t sa = sb + (st^1)*G3_STAGE;
            #pragma unroll
            for (int rep = 0; rep < 4; rep++) {
                int row = lrow + rep*32;
                uint32_t off = (uint32_t)row*128 + 16u*(uint32_t)(lc16 ^ (row & 7));
                cpa16(sa +     0 + off, Ah + (size_t)row*strideA + kk + lc16*8);
                cpa16(sa + 16384 + off, Al + (size_t)row*strideA + kk + lc16*8);
                cpa16(sa + 32768 + off, Bh + (size_t)row*strideB + kk + lc16*8);
                cpa16(sa + 49152 + off, Bl + (size_t)row*strideB + kk + lc16*8);
            }
            asm volatile("cp.async.commit_group;");
            asm volatile("cp.async.wait_group 1;");
        } else {
            asm volatile("cp.async.wait_group 0;");
        }
        __syncthreads();
        gemm3_compute(acc, sb + st*G3_STAGE, rowa_l, ca_l, rowb_l, cb_l);
        __syncthreads();
    }
}

// ---------------------------------------------------------------------------
// Kernel 1a: fp32 -> bf16 hi/lo split for Wo + x (rows of 2048)
// ---------------------------------------------------------------------------
__global__ __launch_bounds__(256) void split_kernel(
    const float* __restrict__ Wo, const float* __restrict__ x)
{
    int row = blockIdx.x;
    int tid = threadIdx.x;
    const float* src;
    __nv_bfloat16 *dhi, *dlo;
    if (row < DD) {
        src = Wo + (size_t)row*SS;
        dhi = g_Whi + (size_t)row*SS; dlo = g_Wlo + (size_t)row*SS;
    } else {
        int r = row - DD;
        src = x + (size_t)r*DD;
        dhi = g_xhi + (size_t)r*DD; dlo = g_xlo + (size_t)r*DD;
    }

    int base = tid * 8;
    float4 f0 = *(const float4*)(src + base);
    float4 f1 = *(const float4*)(src + base + 4);
    float v[8] = {f0.x, f0.y, f0.z, f0.w, f1.x, f1.y, f1.z, f1.w};
    unsigned hw[4], lw[4];
    #pragma unroll
    for (int p = 0; p < 4; p++) {
        __nv_bfloat16 ha, hb, la, lb;
        splitbf(v[2*p], ha, la);
        splitbf(v[2*p+1], hb, lb);
        hw[p] = pack2(ha, hb);
        lw[p] = pack2(la, lb);
    }
    *(uint4*)(dhi + base) = make_uint4(hw[0], hw[1], hw[2], hw[3]);
    *(uint4*)(dlo + base) = make_uint4(lw[0], lw[1], lw[2], lw[3]);
}

// ---------------------------------------------------------------------------
// Kernel 1b: fp32 -> bf16 hi/lo split for Wq/Wk/Wv (flat, 4 elems/thread)
// ---------------------------------------------------------------------------
__global__ __launch_bounds__(256) void splitw_kernel(
    const float* __restrict__ Wq, const float* __restrict__ Wk,
    const float* __restrict__ Wv)
{
    int base = (blockIdx.x*256 + threadIdx.x) * 4;
    int wsel = base >> 18;
    int off  = base & 262143;
    const float* src = (wsel == 0 ? Wq : wsel == 1 ? Wk : Wv) + off;
    float4 f = *(const float4*)src;
    __nv_bfloat16 h0,l0,h1,l1,h2,l2,h3,l3;
    splitbf(f.x,h0,l0); splitbf(f.y,h1,l1); splitbf(f.z,h2,l2); splitbf(f.w,h3,l3);
    *(uint2*)(g_wwhi + base) = make_uint2(pack2(h0,h1), pack2(h2,h3));
    *(uint2*)(g_wwlo + base) = make_uint2(pack2(l0,l1), pack2(l2,l3));
}

// ---------------------------------------------------------------------------
// Kernel 2: QKV projections via HMMA (single-stage). grid (16, 8, 3)
// ---------------------------------------------------------------------------
__global__ __launch_bounds__(256) void qkv_mma_kernel(
    const float* __restrict__ bq, const float* __restrict__ bk,
    const float* __restrict__ bv, int mt_base, int h_base)
{
    int mt = mt_base + blockIdx.x, h = h_base + blockIdx.y, w = blockIdx.z;
    extern __shared__ char sm3[];
    uint32_t sb = smem_u32(sm3);
    int tid = threadIdx.x, lane = tid & 31, wid = tid >> 5;
    int wm = wid & 3, wn = wid >> 2;

    float acc[2][8][4];
    #pragma unroll
    for (int i = 0; i < 2; i++)
        #pragma unroll
        for (int j = 0; j < 8; j++)
            #pragma unroll
            for (int q = 0; q < 4; q++) acc[i][j][q] = 0.f;

    size_t aoff = (size_t)(mt*128)*DD + h*HD;
    size_t boff = (size_t)((w*HH + h)*HD)*HD;
    gemm3_1s(acc, sb, tid, g_xhi + aoff, g_xlo + aoff, DD,
             g_wwhi + boff, g_wwlo + boff, HD, 2);

    const float* bias = (w == 0 ? bq : w == 1 ? bk : bv) + h*HD;
    int b = mt >> 4;
    int bh = b*HH + h;
    int sbase = (mt*128) & (SS - 1);
    int r0w = lane >> 2, cc = (lane & 3)*2;

    if (w < 2) {
        __nv_bfloat16* dh = (w == 0 ? g_qhi : g_khi);
        __nv_bfloat16* dl = (w == 0 ? g_qlo : g_klo);
        #pragma unroll
        for (int i = 0; i < 2; i++) {
            int m0 = wm*32 + i*16 + r0w;
            size_t row0 = ((size_t)bh*SS + sbase + m0)*HD;
            size_t row1 = row0 + (size_t)8*HD;
            #pragma unroll
            for (int j = 0; j < 8; j++) {
                int d0 = wn*64 + j*8 + cc;
                float b0 = bias[d0], b1 = bias[d0+1];
                __nv_bfloat16 ha,la,hb,lb;
                splitbf(acc[i][j][0] + b0, ha, la);
                splitbf(acc[i][j][1] + b1, hb, lb);
                *(unsigned*)(dh + row0 + d0) = pack2(ha, hb);
                *(unsigned*)(dl + row0 + d0) = pack2(la, lb);
                splitbf(acc[i][j][2] + b0, ha, la);
                splitbf(acc[i][j][3] + b1, hb, lb);
                *(unsigned*)(dh + row1 + d0) = pack2(ha, hb);
                *(unsigned*)(dl + row1 + d0) = pack2(la, lb);
            }
        }
    } else {
        __nv_bfloat16* th = (__nv_bfloat16*)sm3;          // [d][m] 128x128
        __nv_bfloat16* tl = th + 128*128;
        #pragma unroll
        for (int i = 0; i < 2; i++) {
            int m0 = wm*32 + i*16 + r0w;
            #pragma unroll
            for (int j = 0; j < 8; j++) {
                int d0 = wn*64 + j*8 + cc;
                float b0 = bias[d0], b1 = bias[d0+1];
                __nv_bfloat16 hh, ll;
                splitbf(acc[i][j][0] + b0, hh, ll);
                th[d0*128 + m0] = hh;         tl[d0*128 + m0] = ll;
                splitbf(acc[i][j][1] + b1, hh, ll);
                th[(d0+1)*128 + m0] = hh;     tl[(d0+1)*128 + m0] = ll;
                splitbf(acc[i][j][2] + b0, hh, ll);
                th[d0*128 + m0 + 8] = hh;     tl[d0*128 + m0 + 8] = ll;
                splitbf(acc[i][j][3] + b1, hh, ll);
                th[(d0+1)*128 + m0 + 8] = hh; tl[(d0+1)*128 + m0 + 8] = ll;
            }
        }
        __syncthreads();
        int d = tid >> 1, half = tid & 1;
        size_t go = ((size_t)bh*HD + d)*SS + sbase + half*64;
        const uint4* s4h = (const uint4*)(th + d*128 + half*64);
        const uint4* s4l = (const uint4*)(tl + d*128 + half*64);
        #pragma unroll
        for (int p = 0; p < 8; p++) {
            *(uint4*)(g_vthi + go + p*8) = s4h[p];
            *(uint4*)(g_vtlo + go + p*8) = s4l[p];
        }
    }
}

// ---------------------------------------------------------------------------
// Kernel 3: score GEMM (single-stage). Triangular grid (136, 8) + bh_base
// ---------------------------------------------------------------------------
__global__ __launch_bounds__(256) void score_gemm_kernel(int bh_base)
{
    int l = blockIdx.x;
    int it = 0, tbase = 0;
    while (l >= tbase + it + 1) { tbase += it + 1; it++; }
    int jt = l - tbase;
    int bh = bh_base + blockIdx.y;

    extern __shared__ char sm3[];
    uint32_t sb = smem_u32(sm3);
    int tid = threadIdx.x, lane = tid & 31, wid = tid >> 5;
    int wm = wid & 3, wn = wid >> 2;

    float acc[2][8][4];
    #pragma unroll
    for (int i = 0; i < 2; i++)
        #pragma unroll
        for (int j = 0; j < 8; j++)
            #pragma unroll
            for (int q = 0; q < 4; q++) acc[i][j][q] = 0.f;

    size_t aoff = ((size_t)bh*SS + it*128)*HD;
    size_t boff = ((size_t)bh*SS + jt*128)*HD;
    gemm3_1s(acc, sb, tid, g_qhi + aoff, g_qlo + aoff, HD,
             g_khi + boff, g_klo + boff, HD, 2);

    const float scale = 0.08838834764831845f;
    int r0w = lane >> 2, cc = (lane & 3) * 2;
    #pragma unroll
    for (int i = 0; i < 2; i++) {
        int m0 = it*128 + wm*32 + i*16 + r0w;
        int m1 = m0 + 8;
        float* row0 = g_sc + ((size_t)bh*SS + m0)*SS + jt*128 + wn*64;
        float* row1 = row0 + (size_t)8*SS;
        #pragma unroll
        for (int j = 0; j < 8; j++) {
            int j0 = jt*128 + wn*64 + j*8 + cc;
            float2 v0, v1;
            v0.x = (j0     <= m0) ? acc[i][j][0]*scale : NEGV;
            v0.y = (j0 + 1 <= m0) ? acc[i][j][1]*scale : NEGV;
            v1.x = (j0     <= m1) ? acc[i][j][2]*scale : NEGV;
            v1.y = (j0 + 1 <= m1) ? acc[i][j][3]*scale : NEGV;
            *(float2*)(row0 + j*8 + cc) = v0;
            *(float2*)(row1 + j*8 + cc) = v1;
        }
    }
}

// ---------------------------------------------------------------------------
// Kernel 4: exact top-k select + fused exp/sum -> UNNORMALIZED bf16 weights
// ---------------------------------------------------------------------------
__device__ __forceinline__ unsigned f2key(float f) {
    unsigned u = __float_as_uint(f);
    return u ^ ((u & 0x80000000u) ? 0xFFFFFFFFu : 0x80000000u);
}
__device__ __forceinline__ float key2f(unsigned k) {
    unsigned u = (k & 0x80000000u) ? (k ^ 0x80000000u) : ~k;
    return __uint_as_float(u);
}

__global__ __launch_bounds__(512) void select_kernel(int bh_base)
{
    __shared__ int hist[16*256];

    int bh   = bh_base + blockIdx.y;
    int s0   = (gridDim.x - 1 - blockIdx.x) * 16;
    int tid  = threadIdx.x;
    int lane = tid & 31, wid = tid >> 5;
    int s    = s0 + wid;
    int nvalid = s + 1;
    int nround = (nvalid + 31) & ~31;

    const float* row = g_sc + ((size_t)bh*SS + s)*SS;
    int* hh = hist + wid*256;

    float lm  = -3.4e38f;
    float thr = -3.4e38f;

    if (s >= KKEEP - 1) {
        unsigned prefix = 0; int K = KKEEP;
        #pragma unroll
        for (int pass = 0; pass < 4; pass++) {
            int shift = 24 - pass*8;
            #pragma unroll
            for (int i = lane; i < 256; i += 32) hh[i] = 0;
            __syncwarp();
            for (int t = lane; t < nround; t += 32) {
                bool valid = (t < nvalid);
                float v = valid ? row[t] : NEGV;
                if (pass == 0 && valid) lm = fmaxf(lm, v);
                unsigned key = f2key(v);
                bool cand = valid &&
                    ((pass == 0) || (((key ^ prefix) >> (shift + 8)) == 0u));
                int bin = cand ? (int)((key >> shift) & 255u) : -1;
                unsigned peers = __match_any_sync(FULLW, bin);
                if (cand && lane == (__ffs(peers) - 1))
                    atomicAdd(&hh[bin], __popc(peers));
            }
            __syncwarp();
            int hv[8]; int ssum = 0;
            #pragma unroll
            for (int i = 0; i < 8; i++) { hv[i] = hh[lane*8 + i]; ssum += hv[i]; }
            int suf = ssum;
            #pragma unroll
            for (int off = 1; off < 32; off <<= 1) {
                int v = __shfl_down_sync(FULLW, suf, off);
                if (lane + off < 32) suf += v;
            }
            int above = suf - ssum;
            int selbin = -1, newK = 0;
            if (suf >= K && above < K) {
                int run = above;
                #pragma unroll
                for (int bb2 = 7; bb2 >= 0; bb2--) {
                    run += hv[bb2];
                    if (run >= K) { selbin = lane*8 + bb2; newK = K - (run - hv[bb2]); break; }
                }
            }
            unsigned msk = __ballot_sync(FULLW, selbin >= 0);
            int src = __ffs(msk) - 1;
            selbin = __shfl_sync(FULLW, selbin, src);
            newK   = __shfl_sync(FULLW, newK,  src);
            prefix |= ((unsigned)selbin) << shift;
            K = newK;
        }
        thr = key2f(prefix);
    } else {
        for (int t = lane; t < nvalid; t += 32) lm = fmaxf(lm, row[t]);
    }

    #pragma unroll
    for (int off = 16; off > 0; off >>= 1)
        lm = fmaxf(lm, __shfl_xor_sync(FULLW, lm, off));

    int CEIL = (s0 & ~127) + 128;
    size_t go = ((size_t)bh*SS + s)*SS;
    float ls = 0.f;
    for (int t4 = lane*4; t4 < CEIL; t4 += 128) {
        float w0 = 0.f, w1 = 0.f, w2 = 0.f, w3 = 0.f;
        if (t4 + 3 < nvalid) {
            float4 v4 = *(const float4*)(row + t4);
            if (v4.x >= thr) w0 = __expf(v4.x - lm);
            if (v4.y >= thr) w1 = __expf(v4.y - lm);
            if (v4.z >= thr) w2 = __expf(v4.z - lm);
            if (v4.w >= thr) w3 = __expf(v4.w - lm);
        } else if (t4 < nvalid) {
            float vv;
            vv = row[t4];
            if (vv >= thr) w0 = __expf(vv - lm);
            if (t4 + 1 < nvalid) { vv = row[t4+1]; if (vv >= thr) w1 = __expf(vv - lm); }
            if (t4 + 2 < nvalid) { vv = row[t4+2]; if (vv >= thr) w2 = __expf(vv - lm); }
        }
        ls += (w0 + w1) + (w2 + w3);
        __nv_bfloat16 h0,l0,h1,l1,h2,l2,h3,l3;
        splitbf(w0,h0,l0); splitbf(w1,h1,l1);
        splitbf(w2,h2,l2); splitbf(w3,h3,l3);
        *(uint2*)(g_wh + go + t4) = make_uint2(pack2(h0,h1), pack2(h2,h3));
        *(uint2*)(g_wl + go + t4) = make_uint2(pack2(l0,l1), pack2(l2,l3));
    }
    #pragma unroll
    for (int off = 16; off > 0; off >>= 1)
        ls += __shfl_xor_sync(FULLW, ls, off);
    if (lane == 0) g_rsv[(size_t)bh*SS + s] = 1.f / ls;
}

// ---------------------------------------------------------------------------
// Kernel 5: AV GEMM (transposed, double-buffered)
// ---------------------------------------------------------------------------
__global__ __launch_bounds__(256) void av_gemm_kernel(int bh_base)
{
    int st = gridDim.x - 1 - blockIdx.x;
    int bh = bh_base + blockIdx.y;

    extern __shared__ char sm3[];
    uint32_t sb = smem_u32(sm3);
    int tid = threadIdx.x, lane = tid & 31, wid = tid >> 5;
    int wm = wid & 3, wn = wid >> 2;

    float acc[2][8][4];
    #pragma unroll
    for (int i = 0; i < 2; i++)
        #pragma unroll
        for (int j = 0; j < 8; j++)
            #pragma unroll
            for (int q = 0; q < 4; q++) acc[i][j][q] = 0.f;

    size_t aoff = (size_t)bh*HD*SS;
    size_t boff = ((size_t)bh*SS + st*128)*SS;
    gemm3_core(acc, sb, tid, g_vthi + aoff, g_vtlo + aoff, SS,
               g_wh + boff, g_wl + boff, SS, 2*(st + 1));

    int b = bh >> 4, h = bh & 15;
    int r0w = lane >> 2, cc = (lane & 3) * 2;
    const float* rsvp = g_rsv + (size_t)bh*SS;
    #pragma unroll
    for (int i = 0; i < 2; i++) {
        int d0 = wm*32 + i*16 + r0w;
        size_t rowA = ((size_t)b*DD + h*HD + d0)*SS;
        size_t rowB = rowA + (size_t)8*SS;
        #pragma unroll
        for (int j = 0; j < 8; j++) {
            int s_col = st*128 + wn*64 + j*8 + cc;
            float r0 = rsvp[s_col], r1 = rsvp[s_col + 1];
            __nv_bfloat16 h0,l0,h1,l1;
            splitbf(acc[i][j][0]*r0, h0, l0);
            splitbf(acc[i][j][1]*r1, h1, l1);
            *(unsigned*)(g_Ahi + rowA + s_col) = pack2(h0, h1);
            *(unsigned*)(g_Alo + rowA + s_col) = pack2(l0, l1);
            splitbf(acc[i][j][2]*r0, h0, l0);
            splitbf(acc[i][j][3]*r1, h1, l1);
            *(unsigned*)(g_Ahi + rowB + s_col) = pack2(h0, h1);
            *(unsigned*)(g_Alo + rowB + s_col) = pack2(l0, l1);
        }
    }
}

// ---------------------------------------------------------------------------
// Kernel 6: proj GEMM (3-stage pipeline), per-batch. grid (16, 16)
// ---------------------------------------------------------------------------
#define PJ_STAGE 32768
#define PJ_SMEM  (3*PJ_STAGE)

__global__ __launch_bounds__(256) void proj_mma_kernel(
    const float* __restrict__ bo, float* __restrict__ out, int b)
{
    extern __shared__ char psm[];
    uint32_t sb = smem_u32(psm);

    int tid = threadIdx.x, lane = tid & 31, wid = tid >> 5;
    int wm = wid & 3, wn = wid >> 2;
    int nt = blockIdx.x, mt = blockIdx.y;

    const __nv_bfloat16* Abase   = g_Ahi + ((size_t)b*DD + mt*128)*SS;
    const __nv_bfloat16* AbaseLo = g_Alo + ((size_t)b*DD + mt*128)*SS;
    const __nv_bfloat16* Wbase   = g_Whi + (size_t)(nt*128)*SS;
    const __nv_bfloat16* WbaseLo = g_Wlo + (size_t)(nt*128)*SS;

    int lrow = tid >> 3, lc16 = tid & 7;

    float acc[2][8][4];
    #pragma unroll
    for (int i = 0; i < 2; i++)
        #pragma unroll
        for (int j = 0; j < 8; j++)
            #pragma unroll
            for (int q = 0; q < 4; q++) acc[i][j][q] = 0.f;

    int rowa_l = wm*32 + (lane & 15);
    int ca_l   = (lane >> 4);
    int rowb_l = wn*64 + (lane & 7) + ((lane >> 4) << 3);
    int cb_l   = (lane >> 3) & 1;

    const int NC = 96;

    auto load_chunk = [&](int c, int stg) {
        int seg = c >> 5, kk = (c & 31) * 64;
        const __nv_bfloat16* As = (seg == 1 ? AbaseLo : Abase);
        const __nv_bfloat16* Bs = (seg == 2 ? WbaseLo : Wbase);
        uint32_t sa = sb + stg*PJ_STAGE, sbB = sa + 16384;
        #pragma unroll
        for (int rep = 0; rep < 4; rep++) {
            int row = lrow + rep*32;
            uint32_t off = (uint32_t)row*128 + 16u*(uint32_t)(lc16 ^ (row & 7));
            cpa16(sa  + off, As + (size_t)row*SS + kk + lc16*8);
            cpa16(sbB + off, Bs + (size_t)row*SS + kk + lc16*8);
        }
        asm volatile("cp.async.commit_group;");
    };

    load_chunk(0, 0);
    load_chunk(1, 1);

    for (int c = 0; c < NC; c++) {
        int st = c % 3;
        if (c + 2 < NC) {
            load_chunk(c + 2, (c + 2) % 3);
            asm volatile("cp.async.wait_group 2;");
        } else if (c + 1 < NC) {
            asm volatile("cp.async.wait_group 1;");
        } else {
            asm volatile("cp.async.wait_group 0;");
        }
        __syncthreads();

        uint32_t sa = sb + st*PJ_STAGE, sbB = sa + 16384;
        #pragma unroll
        for (int kstep = 0; kstep < 4; kstep++) {
            uint32_t afr[2][4];
            #pragma unroll
            for (int i = 0; i < 2; i++) {
                int row = rowa_l + i*16;
                int c16 = kstep*2 + ca_l;
                ldsm4(afr[i], sa + (uint32_t)row*128 + 16u*(uint32_t)(c16 ^ (row & 7)));
            }
            uint32_t bfr[4][4];
            #pragma unroll
            for (int j4 = 0; j4 < 4; j4++) {
                int row = rowb_l + j4*16;
                int c16 = kstep*2 + cb_l;
                ldsm4(bfr[j4], sbB + (uint32_t)row*128 + 16u*(uint32_t)(c16 ^ (row & 7)));
            }
            #pragma unroll
            for (int i = 0; i < 2; i++)
                #pragma unroll
                for (int j4 = 0; j4 < 4; j4++) {
                    mma16816(acc[i][2*j4+0], afr[i], bfr[j4][0], bfr[j4][1]);
                    mma16816(acc[i][2*j4+1], afr[i], bfr[j4][2], bfr[j4][3]);
                }
        }
        __syncthreads();
    }

    int r0w = lane >> 2, cc = (lane & 3) * 2;
    const float* bop = bo + nt*128 + wn*64;
    #pragma unroll
    for (int i = 0; i < 2; i++) {
        int m = mt*128 + wm*32 + i*16 + r0w;
        float* row0 = out + ((size_t)b*DD + m)*DD + nt*128 + wn*64;
        float* row1 = row0 + (size_t)8*DD;
        #pragma unroll
        for (int j = 0; j < 8; j++) {
            float2 bb = *(const float2*)(bop + j*8 + cc);
            float2 v0 = make_float2(acc[i][j][0] + bb.x, acc[i][j][1] + bb.y);
            float2 v1 = make_float2(acc[i][j][2] + bb.x, acc[i][j][3] + bb.y);
            *(float2*)(row0 + j*8 + cc) = v0;
            *(float2*)(row1 + j*8 + cc) = v1;
        }
    }
}

// ---------------------------------------------------------------------------
// Host: 4-stream pipeline over (batch, head-half); static pre-capture streams
// ---------------------------------------------------------------------------
static cudaStream_t g_st[3] = {nullptr, nullptr, nullptr};
static cudaEvent_t  g_evF = nullptr, g_evA0 = nullptr, g_evA1 = nullptr, g_evJ = nullptr;
namespace {
struct StreamInit {
    StreamInit() {
        for (int i = 0; i < 3; i++)
            cudaStreamCreateWithFlags(&g_st[i], cudaStreamNonBlocking);
        cudaEventCreateWithFlags(&g_evF, cudaEventDisableTiming);
        cudaEventCreateWithFlags(&g_evA0, cudaEventDisableTiming);
        cudaEventCreateWithFlags(&g_evA1, cudaEventDisableTiming);
        cudaEventCreateWithFlags(&g_evJ, cudaEventDisableTiming);
    }
};
static StreamInit g_stream_init;
}

extern "C" void kernel_launch(void* const* d_in, const int* in_sizes, int n_in,
                              void* d_out, int out_size)
{
    const float* x  = (const float*)d_in[0];
    const float* Wq = (const float*)d_in[2];
    const float* Wk = (const float*)d_in[3];
    const float* Wv = (const float*)d_in[4];
    const float* bq = (const float*)d_in[5];
    const float* bk = (const float*)d_in[6];
    const float* bv = (const float*)d_in[7];
    const float* Wo = (const float*)d_in[8];
    const float* bo = (const float*)d_in[9];
    float* out = (float*)d_out;

    if (!g_st[0]) {
        for (int i = 0; i < 3; i++)
            cudaStreamCreateWithFlags(&g_st[i], cudaStreamNonBlocking);
        cudaEventCreateWithFlags(&g_evF, cudaEventDisableTiming);
        cudaEventCreateWithFlags(&g_evA0, cudaEventDisableTiming);
        cudaEventCreateWithFlags(&g_evA1, cudaEventDisableTiming);
        cudaEventCreateWithFlags(&g_evJ, cudaEventDisableTiming);
    }

    cudaFuncSetAttribute(qkv_mma_kernel,    cudaFuncAttributeMaxDynamicSharedMemorySize, G1_SMEM);
    cudaFuncSetAttribute(score_gemm_kernel, cudaFuncAttributeMaxDynamicSharedMemorySize, G1_SMEM);
    cudaFuncSetAttribute(av_gemm_kernel,    cudaFuncAttributeMaxDynamicSharedMemorySize, G3_SMEM);
    cudaFuncSetAttribute(proj_mma_kernel,   cudaFuncAttributeMaxDynamicSharedMemorySize, PJ_SMEM);

    // shared prologue on capture stream
    split_kernel<<<dim3(DD + BB*SS), 256>>>(Wo, x);
    splitw_kernel<<<dim3(768), 256>>>(Wq, Wk, Wv);
    cudaEventRecord(g_evF, 0);
    for (int i = 0; i < 3; i++) cudaStreamWaitEvent(g_st[i], g_evF, 0);

    // 4 chains: (b, hh) -> stream {0, g_st[0], g_st[1], g_st[2]}
    for (int chain = 0; chain < 4; chain++) {
        int b = chain >> 1, hh = chain & 1;
        cudaStream_t strm = (chain == 0) ? (cudaStream_t)0 : g_st[chain - 1];
        int bh0 = b*HH + hh*8;
        qkv_mma_kernel<<<dim3(16, 8, 3), 256, G1_SMEM, strm>>>(bq, bk, bv, b*16, hh*8);
        score_gemm_kernel<<<dim3(136, 8), 256, G1_SMEM, strm>>>(bh0);
        select_kernel<<<dim3(SS/16, 8), 512, 0, strm>>>(bh0);
        av_gemm_kernel<<<dim3(16, 8), 256, G3_SMEM, strm>>>(bh0);
    }

    // proj b=0: join chain(0,1) [g_st[0]] into capture stream
    cudaEventRecord(g_evA0, g_st[0]);
    cudaStreamWaitEvent(0, g_evA0, 0);
    proj_mma_kernel<<<dim3(16, 16), 256, PJ_SMEM, 0>>>(bo, out, 0);

    // proj b=1: join chain(1,1) [g_st[2]] into g_st[1]
    cudaEventRecord(g_evA1, g_st[2]);
    cudaStreamWaitEvent(g_st[1], g_evA1, 0);
    proj_mma_kernel<<<dim3(16, 16), 256, PJ_SMEM, g_st[1]>>>(bo, out, 1);

    cudaEventRecord(g_evJ, g_st[1]);
    cudaStreamWaitEvent(0, g_evJ, 0);
}

// round 15
// speedup vs baseline: 1.0868x; 1.0868x over previous
#include <cuda_runtime.h>
#include <cuda_bf16.h>
#include <cstdint>
#include <math.h>

#define BB 2
#define HH 16
#define SS 2048
#define HD 128
#define DD 2048
#define KKEEP 819
#define NEGV -1e9f
#define FULLW 0xffffffffu

// ---------------- scratch (device globals; no allocation allowed) ----------
__device__ __nv_bfloat16 g_qhi [BB*HH*SS*HD];  // [bh][s][d]
__device__ __nv_bfloat16 g_qlo [BB*HH*SS*HD];
__device__ __nv_bfloat16 g_khi [BB*HH*SS*HD];  // [bh][t][d]
__device__ __nv_bfloat16 g_klo [BB*HH*SS*HD];
__device__ __nv_bfloat16 g_vthi[BB*HH*HD*SS];  // [bh][d][t]
__device__ __nv_bfloat16 g_vtlo[BB*HH*HD*SS];

__device__ __nv_bfloat16 g_xhi[(size_t)BB*SS*DD];   // x split [b][s][D]
__device__ __nv_bfloat16 g_xlo[(size_t)BB*SS*DD];
__device__ __nv_bfloat16 g_wwhi[3*HH*HD*HD];        // Wq/Wk/Wv split [w][h][e][k]
__device__ __nv_bfloat16 g_wwlo[3*HH*HD*HD];

__device__ float         g_sc [(size_t)BB*HH*SS*SS];   // scores [bh][s][t]
__device__ __nv_bfloat16 g_wh [(size_t)BB*HH*SS*SS];   // UNNORMALIZED weights hi
__device__ __nv_bfloat16 g_wl [(size_t)BB*HH*SS*SS];   // UNNORMALIZED weights lo
__device__ float         g_rsv[(size_t)BB*HH*SS];      // per-row 1/sum

// proj operands (A written directly by av_gemm epilogue)
__device__ __nv_bfloat16 g_Ahi[(size_t)BB*DD*SS];      // [b][i][s]
__device__ __nv_bfloat16 g_Alo[(size_t)BB*DD*SS];
__device__ __nv_bfloat16 g_Whi[(size_t)DD*SS];
__device__ __nv_bfloat16 g_Wlo[(size_t)DD*SS];

// ---------------- common helpers -------------------------------------------
__device__ __forceinline__ uint32_t smem_u32(const void* p) {
    uint32_t a;
    asm("{ .reg .u64 t; cvta.to.shared.u64 t, %1; cvt.u32.u64 %0, t; }" : "=r"(a) : "l"(p));
    return a;
}
__device__ __forceinline__ void cpa16(uint32_t s, const void* g) {
    asm volatile("cp.async.cg.shared.global [%0], [%1], 16;" :: "r"(s), "l"(g));
}
__device__ __forceinline__ void ldsm4(uint32_t* r, uint32_t a) {
    asm volatile("ldmatrix.sync.aligned.m8n8.x4.shared.b16 {%0,%1,%2,%3}, [%4];"
                 : "=r"(r[0]), "=r"(r[1]), "=r"(r[2]), "=r"(r[3]) : "r"(a));
}
__device__ __forceinline__ void mma16816(float* c, const uint32_t* a, uint32_t b0, uint32_t b1) {
    asm volatile("mma.sync.aligned.m16n8k16.row.col.f32.bf16.bf16.f32 "
                 "{%0,%1,%2,%3}, {%4,%5,%6,%7}, {%8,%9}, {%0,%1,%2,%3};"
                 : "+f"(c[0]), "+f"(c[1]), "+f"(c[2]), "+f"(c[3])
                 : "r"(a[0]), "r"(a[1]), "r"(a[2]), "r"(a[3]), "r"(b0), "r"(b1));
}
__device__ __forceinline__ void splitbf(float a, __nv_bfloat16& h, __nv_bfloat16& l) {
    h = __float2bfloat16(a);
    l = __float2bfloat16(a - __bfloat162float(h));
}
__device__ __forceinline__ unsigned pack2(__nv_bfloat16 a, __nv_bfloat16 b) {
    return (unsigned)*(unsigned short*)&a | ((unsigned)*(unsigned short*)&b << 16);
}

// ---------------------------------------------------------------------------
// gemm3 core: 128x128 tile, K in 64-chunks, 3 terms (AhBh + AlBh + AhBl).
// ---------------------------------------------------------------------------
#define G3_STAGE 65536
#define G3_SMEM  (2*G3_STAGE)

__device__ __forceinline__ void gemm3_core(
    float (*acc)[8][4], uint32_t sb, int tid,
    const __nv_bfloat16* Ah, const __nv_bfloat16* Al, size_t strideA,
    const __nv_bfloat16* Bh, const __nv_bfloat16* Bl, size_t strideB,
    int NC)
{
    int lane = tid & 31, wid = tid >> 5;
    int wm = wid & 3, wn = wid >> 2;
    int lrow = tid >> 3, lc16 = tid & 7;

    int rowa_l = wm*32 + (lane & 15);
    int ca_l   = (lane >> 4);
    int rowb_l = wn*64 + (lane & 7) + ((lane >> 4) << 3);
    int cb_l   = (lane >> 3) & 1;

    {
        uint32_t sa = sb;
        #pragma unroll
        for (int rep = 0; rep < 4; rep++) {
            int row = lrow + rep*32;
            uint32_t off = (uint32_t)row*128 + 16u*(uint32_t)(lc16 ^ (row & 7));
            cpa16(sa +     0 + off, Ah + (size_t)row*strideA + lc16*8);
            cpa16(sa + 16384 + off, Al + (size_t)row*strideA + lc16*8);
            cpa16(sa + 32768 + off, Bh + (size_t)row*strideB + lc16*8);
            cpa16(sa + 49152 + off, Bl + (size_t)row*strideB + lc16*8);
        }
        asm volatile("cp.async.commit_group;");
    }

    for (int c = 0; c < NC; c++) {
        int st = c & 1;
        if (c + 1 < NC) {
            int kk = (c + 1) * 64;
            uint32_t sa = sb + (st^1)*G3_STAGE;
            #pragma unroll
            for (int rep = 0; rep < 4; rep++) {
                int row = lrow + rep*32;
                uint32_t off = (uint32_t)row*128 + 16u*(uint32_t)(lc16 ^ (row & 7));
                cpa16(sa +     0 + off, Ah + (size_t)row*strideA + kk + lc16*8);
                cpa16(sa + 16384 + off, Al + (size_t)row*strideA + kk + lc16*8);
                cpa16(sa + 32768 + off, Bh + (size_t)row*strideB + kk + lc16*8);
                cpa16(sa + 49152 + off, Bl + (size_t)row*strideB + kk + lc16*8);
            }
            asm volatile("cp.async.commit_group;");
            asm volatile("cp.async.wait_group 1;");
        } else {
            asm volatile("cp.async.wait_group 0;");
        }
        __syncthreads();

        uint32_t sa = sb + st*G3_STAGE;
        #pragma unroll
        for (int kstep = 0; kstep < 4; kstep++) {
            uint32_t ah[2][4], al[2][4];
            #pragma unroll
            for (int i = 0; i < 2; i++) {
                int row = rowa_l + i*16;
                int c16 = kstep*2 + ca_l;
                uint32_t off = (uint32_t)row*128 + 16u*(uint32_t)(c16 ^ (row & 7));
                ldsm4(ah[i], sa + off);
                ldsm4(al[i], sa + 16384 + off);
            }
            #pragma unroll
            for (int j4 = 0; j4 < 4; j4++) {
                int row = rowb_l + j4*16;
                int c16 = kstep*2 + cb_l;
                uint32_t off = (uint32_t)row*128 + 16u*(uint32_t)(c16 ^ (row & 7));
                uint32_t bhf[4], blf[4];
                ldsm4(bhf, sa + 32768 + off);
                ldsm4(blf, sa + 49152 + off);
                #pragma unroll
                for (int i = 0; i < 2; i++) {
                    mma16816(acc[i][2*j4+0], ah[i], bhf[0], bhf[1]);
                    mma16816(acc[i][2*j4+1], ah[i], bhf[2], bhf[3]);
                    mma16816(acc[i][2*j4+0], al[i], bhf[0], bhf[1]);
                    mma16816(acc[i][2*j4+1], al[i], bhf[2], bhf[3]);
                    mma16816(acc[i][2*j4+0], ah[i], blf[0], blf[1]);
                    mma16816(acc[i][2*j4+1], ah[i], blf[2], blf[3]);
                }
            }
        }
        __syncthreads();
    }
}

// ---------------------------------------------------------------------------
// Kernel 1a: fp32 -> bf16 hi/lo split for Wo + x (rows of 2048)
// ---------------------------------------------------------------------------
__global__ __launch_bounds__(256) void split_kernel(
    const float* __restrict__ Wo, const float* __restrict__ x)
{
    int row = blockIdx.x;
    int tid = threadIdx.x;
    const float* src;
    __nv_bfloat16 *dhi, *dlo;
    if (row < DD) {
        src = Wo + (size_t)row*SS;
        dhi = g_Whi + (size_t)row*SS; dlo = g_Wlo + (size_t)row*SS;
    } else {
        int r = row - DD;
        src = x + (size_t)r*DD;
        dhi = g_xhi + (size_t)r*DD; dlo = g_xlo + (size_t)r*DD;
    }

    int base = tid * 8;
    float4 f0 = *(const float4*)(src + base);
    float4 f1 = *(const float4*)(src + base + 4);
    float v[8] = {f0.x, f0.y, f0.z, f0.w, f1.x, f1.y, f1.z, f1.w};
    unsigned hw[4], lw[4];
    #pragma unroll
    for (int p = 0; p < 4; p++) {
        __nv_bfloat16 ha, hb, la, lb;
        splitbf(v[2*p], ha, la);
        splitbf(v[2*p+1], hb, lb);
        hw[p] = pack2(ha, hb);
        lw[p] = pack2(la, lb);
    }
    *(uint4*)(dhi + base) = make_uint4(hw[0], hw[1], hw[2], hw[3]);
    *(uint4*)(dlo + base) = make_uint4(lw[0], lw[1], lw[2], lw[3]);
}

// ---------------------------------------------------------------------------
// Kernel 1b: fp32 -> bf16 hi/lo split for Wq/Wk/Wv (flat, 4 elems/thread)
// ---------------------------------------------------------------------------
__global__ __launch_bounds__(256) void splitw_kernel(
    const float* __restrict__ Wq, const float* __restrict__ Wk,
    const float* __restrict__ Wv)
{
    int base = (blockIdx.x*256 + threadIdx.x) * 4;
    int wsel = base >> 18;
    int off  = base & 262143;
    const float* src = (wsel == 0 ? Wq : wsel == 1 ? Wk : Wv) + off;
    float4 f = *(const float4*)src;
    __nv_bfloat16 h0,l0,h1,l1,h2,l2,h3,l3;
    splitbf(f.x,h0,l0); splitbf(f.y,h1,l1); splitbf(f.z,h2,l2); splitbf(f.w,h3,l3);
    *(uint2*)(g_wwhi + base) = make_uint2(pack2(h0,h1), pack2(h2,h3));
    *(uint2*)(g_wwlo + base) = make_uint2(pack2(l0,l1), pack2(l2,l3));
}

// ---------------------------------------------------------------------------
// Kernel 2: QKV projections via HMMA. grid (16, HH, 3) + mt_base
// ---------------------------------------------------------------------------
__global__ __launch_bounds__(256) void qkv_mma_kernel(
    const float* __restrict__ bq, const float* __restrict__ bk,
    const float* __restrict__ bv, int mt_base)
{
    int mt = mt_base + blockIdx.x, h = blockIdx.y, w = blockIdx.z;
    extern __shared__ char sm3[];
    uint32_t sb = smem_u32(sm3);
    int tid = threadIdx.x, lane = tid & 31, wid = tid >> 5;
    int wm = wid & 3, wn = wid >> 2;

    float acc[2][8][4];
    #pragma unroll
    for (int i = 0; i < 2; i++)
        #pragma unroll
        for (int j = 0; j < 8; j++)
            #pragma unroll
            for (int q = 0; q < 4; q++) acc[i][j][q] = 0.f;

    size_t aoff = (size_t)(mt*128)*DD + h*HD;
    size_t boff = (size_t)((w*HH + h)*HD)*HD;
    gemm3_core(acc, sb, tid, g_xhi + aoff, g_xlo + aoff, DD,
               g_wwhi + boff, g_wwlo + boff, HD, 2);

    const float* bias = (w == 0 ? bq : w == 1 ? bk : bv) + h*HD;
    int b = mt >> 4;
    int bh = b*HH + h;
    int sbase = (mt*128) & (SS - 1);
    int r0w = lane >> 2, cc = (lane & 3)*2;

    if (w < 2) {
        __nv_bfloat16* dh = (w == 0 ? g_qhi : g_khi);
        __nv_bfloat16* dl = (w == 0 ? g_qlo : g_klo);
        #pragma unroll
        for (int i = 0; i < 2; i++) {
            int m0 = wm*32 + i*16 + r0w;
            size_t row0 = ((size_t)bh*SS + sbase + m0)*HD;
            size_t row1 = row0 + (size_t)8*HD;
            #pragma unroll
            for (int j = 0; j < 8; j++) {
                int d0 = wn*64 + j*8 + cc;
                float b0 = bias[d0], b1 = bias[d0+1];
                __nv_bfloat16 ha,la,hb,lb;
                splitbf(acc[i][j][0] + b0, ha, la);
                splitbf(acc[i][j][1] + b1, hb, lb);
                *(unsigned*)(dh + row0 + d0) = pack2(ha, hb);
                *(unsigned*)(dl + row0 + d0) = pack2(la, lb);
                splitbf(acc[i][j][2] + b0, ha, la);
                splitbf(acc[i][j][3] + b1, hb, lb);
                *(unsigned*)(dh + row1 + d0) = pack2(ha, hb);
                *(unsigned*)(dl + row1 + d0) = pack2(la, lb);
            }
        }
    } else {
        __nv_bfloat16* th = (__nv_bfloat16*)sm3;          // [d][m] 128x128
        __nv_bfloat16* tl = th + 128*128;
        #pragma unroll
        for (int i = 0; i < 2; i++) {
            int m0 = wm*32 + i*16 + r0w;
            #pragma unroll
            for (int j = 0; j < 8; j++) {
                int d0 = wn*64 + j*8 + cc;
                float b0 = bias[d0], b1 = bias[d0+1];
                __nv_bfloat16 hh, ll;
                splitbf(acc[i][j][0] + b0, hh, ll);
                th[d0*128 + m0] = hh;         tl[d0*128 + m0] = ll;
                splitbf(acc[i][j][1] + b1, hh, ll);
                th[(d0+1)*128 + m0] = hh;     tl[(d0+1)*128 + m0] = ll;
                splitbf(acc[i][j][2] + b0, hh, ll);
                th[d0*128 + m0 + 8] = hh;     tl[d0*128 + m0 + 8] = ll;
                splitbf(acc[i][j][3] + b1, hh, ll);
                th[(d0+1)*128 + m0 + 8] = hh; tl[(d0+1)*128 + m0 + 8] = ll;
            }
        }
        __syncthreads();
        int d = tid >> 1, half = tid & 1;
        size_t go = ((size_t)bh*HD + d)*SS + sbase + half*64;
        const uint4* s4h = (const uint4*)(th + d*128 + half*64);
        const uint4* s4l = (const uint4*)(tl + d*128 + half*64);
        #pragma unroll
        for (int p = 0; p < 8; p++) {
            *(uint4*)(g_vthi + go + p*8) = s4h[p];
            *(uint4*)(g_vtlo + go + p*8) = s4l[p];
        }
    }
}

// ---------------------------------------------------------------------------
// Kernel 3: score GEMM. Triangular grid (136, HH) + bh_base
// ---------------------------------------------------------------------------
__global__ __launch_bounds__(256) void score_gemm_kernel(int bh_base)
{
    int l = blockIdx.x;
    int it = 0, tbase = 0;
    while (l >= tbase + it + 1) { tbase += it + 1; it++; }
    int jt = l - tbase;
    int bh = bh_base + blockIdx.y;

    extern __shared__ char sm3[];
    uint32_t sb = smem_u32(sm3);
    int tid = threadIdx.x, lane = tid & 31, wid = tid >> 5;
    int wm = wid & 3, wn = wid >> 2;

    float acc[2][8][4];
    #pragma unroll
    for (int i = 0; i < 2; i++)
        #pragma unroll
        for (int j = 0; j < 8; j++)
            #pragma unroll
            for (int q = 0; q < 4; q++) acc[i][j][q] = 0.f;

    size_t aoff = ((size_t)bh*SS + it*128)*HD;
    size_t boff = ((size_t)bh*SS + jt*128)*HD;
    gemm3_core(acc, sb, tid, g_qhi + aoff, g_qlo + aoff, HD,
               g_khi + boff, g_klo + boff, HD, 2);

    const float scale = 0.08838834764831845f;
    int r0w = lane >> 2, cc = (lane & 3) * 2;
    #pragma unroll
    for (int i = 0; i < 2; i++) {
        int m0 = it*128 + wm*32 + i*16 + r0w;
        int m1 = m0 + 8;
        float* row0 = g_sc + ((size_t)bh*SS + m0)*SS + jt*128 + wn*64;
        float* row1 = row0 + (size_t)8*SS;
        #pragma unroll
        for (int j = 0; j < 8; j++) {
            int j0 = jt*128 + wn*64 + j*8 + cc;
            float2 v0, v1;
            v0.x = (j0     <= m0) ? acc[i][j][0]*scale : NEGV;
            v0.y = (j0 + 1 <= m0) ? acc[i][j][1]*scale : NEGV;
            v1.x = (j0     <= m1) ? acc[i][j][2]*scale : NEGV;
            v1.y = (j0 + 1 <= m1) ? acc[i][j][3]*scale : NEGV;
            *(float2*)(row0 + j*8 + cc) = v0;
            *(float2*)(row1 + j*8 + cc) = v1;
        }
    }
}

// ---------------------------------------------------------------------------
// Kernel 4: exact top-k select (early-exit radix) + fused exp/sum
// -> UNNORMALIZED bf16 weights. Threshold only needs to separate the kth set,
// so exit as soon as the selected bin's count equals the remaining K.
// ---------------------------------------------------------------------------
__device__ __forceinline__ unsigned f2key(float f) {
    unsigned u = __float_as_uint(f);
    return u ^ ((u & 0x80000000u) ? 0xFFFFFFFFu : 0x80000000u);
}
__device__ __forceinline__ float key2f(unsigned k) {
    unsigned u = (k & 0x80000000u) ? (k ^ 0x80000000u) : ~k;
    return __uint_as_float(u);
}

__global__ __launch_bounds__(512) void select_kernel(int bh_base)
{
    __shared__ int hist[16*256];

    int bh   = bh_base + blockIdx.y;
    int s0   = (gridDim.x - 1 - blockIdx.x) * 16;
    int tid  = threadIdx.x;
    int lane = tid & 31, wid = tid >> 5;
    int s    = s0 + wid;
    int nvalid = s + 1;
    int nround = (nvalid + 31) & ~31;

    const float* row = g_sc + ((size_t)bh*SS + s)*SS;
    int* hh = hist + wid*256;

    float lm  = -3.4e38f;
    float thr = -3.4e38f;

    if (s >= KKEEP - 1) {
        unsigned prefix = 0; int K = KKEEP;
        for (int pass = 0; pass < 4; pass++) {
            int shift = 24 - pass*8;
            #pragma unroll
            for (int i = lane; i < 256; i += 32) hh[i] = 0;
            __syncwarp();
            for (int t = lane; t < nround; t += 32) {
                bool valid = (t < nvalid);
                float v = valid ? row[t] : NEGV;
                if (pass == 0 && valid) lm = fmaxf(lm, v);
                unsigned key = f2key(v);
                bool cand = valid &&
                    ((pass == 0) || (((key ^ prefix) >> (shift + 8)) == 0u));
                int bin = cand ? (int)((key >> shift) & 255u) : -1;
                unsigned peers = __match_any_sync(FULLW, bin);
                if (cand && lane == (__ffs(peers) - 1))
                    atomicAdd(&hh[bin], __popc(peers));
            }
            __syncwarp();
            int hv[8]; int ssum = 0;
            #pragma unroll
            for (int i = 0; i < 8; i++) { hv[i] = hh[lane*8 + i]; ssum += hv[i]; }
            int suf = ssum;
            #pragma unroll
            for (int off = 1; off < 32; off <<= 1) {
                int v = __shfl_down_sync(FULLW, suf, off);
                if (lane + off < 32) suf += v;
            }
            int above = suf - ssum;
            int selbin = -1, newK = 0, cnt = 0;
            if (suf >= K && above < K) {
                int run = above;
                #pragma unroll
                for (int bb2 = 7; bb2 >= 0; bb2--) {
                    run += hv[bb2];
                    if (run >= K) {
                        selbin = lane*8 + bb2;
                        newK = K - (run - hv[bb2]);
                        cnt = hv[bb2];
                        break;
                    }
                }
            }
            unsigned msk = __ballot_sync(FULLW, selbin >= 0);
            int src = __ffs(msk) - 1;
            selbin = __shfl_sync(FULLW, selbin, src);
            newK   = __shfl_sync(FULLW, newK,  src);
            cnt    = __shfl_sync(FULLW, cnt,   src);
            prefix |= ((unsigned)selbin) << shift;
            K = newK;
            // early exit: whole bin is kept -> bin floor is a valid threshold
            if (newK == cnt) break;
        }
        thr = key2f(prefix);   // un-set low bits = bin floor
    } else {
        for (int t = lane; t < nvalid; t += 32) lm = fmaxf(lm, row[t]);
    }

    #pragma unroll
    for (int off = 16; off > 0; off >>= 1)
        lm = fmaxf(lm, __shfl_xor_sync(FULLW, lm, off));

    int CEIL = (s0 & ~127) + 128;
    size_t go = ((size_t)bh*SS + s)*SS;
    float ls = 0.f;
    for (int t4 = lane*4; t4 < CEIL; t4 += 128) {
        float w0 = 0.f, w1 = 0.f, w2 = 0.f, w3 = 0.f;
        if (t4 + 3 < nvalid) {
            float4 v4 = *(const float4*)(row + t4);
            if (v4.x >= thr) w0 = __expf(v4.x - lm);
            if (v4.y >= thr) w1 = __expf(v4.y - lm);
            if (v4.z >= thr) w2 = __expf(v4.z - lm);
            if (v4.w >= thr) w3 = __expf(v4.w - lm);
        } else if (t4 < nvalid) {
            float vv;
            vv = row[t4];
            if (vv >= thr) w0 = __expf(vv - lm);
            if (t4 + 1 < nvalid) { vv = row[t4+1]; if (vv >= thr) w1 = __expf(vv - lm); }
            if (t4 + 2 < nvalid) { vv = row[t4+2]; if (vv >= thr) w2 = __expf(vv - lm); }
        }
        ls += (w0 + w1) + (w2 + w3);
        __nv_bfloat16 h0,l0,h1,l1,h2,l2,h3,l3;
        splitbf(w0,h0,l0); splitbf(w1,h1,l1);
        splitbf(w2,h2,l2); splitbf(w3,h3,l3);
        *(uint2*)(g_wh + go + t4) = make_uint2(pack2(h0,h1), pack2(h2,h3));
        *(uint2*)(g_wl + go + t4) = make_uint2(pack2(l0,l1), pack2(l2,l3));
    }
    #pragma unroll
    for (int off = 16; off > 0; off >>= 1)
        ls += __shfl_xor_sync(FULLW, ls, off);
    if (lane == 0) g_rsv[(size_t)bh*SS + s] = 1.f / ls;
}

// ---------------------------------------------------------------------------
// Kernel 5: AV GEMM (transposed): outT[d, s] = rsv[s] * sum_t V^T[d,t]*W[s,t]
// ---------------------------------------------------------------------------
__global__ __launch_bounds__(256) void av_gemm_kernel(int bh_base)
{
    int st = gridDim.x - 1 - blockIdx.x;
    int bh = bh_base + blockIdx.y;

    extern __shared__ char sm3[];
    uint32_t sb = smem_u32(sm3);
    int tid = threadIdx.x, lane = tid & 31, wid = tid >> 5;
    int wm = wid & 3, wn = wid >> 2;

    float acc[2][8][4];
    #pragma unroll
    for (int i = 0; i < 2; i++)
        #pragma unroll
        for (int j = 0; j < 8; j++)
            #pragma unroll
            for (int q = 0; q < 4; q++) acc[i][j][q] = 0.f;

    size_t aoff = (size_t)bh*HD*SS;
    size_t boff = ((size_t)bh*SS + st*128)*SS;
    gemm3_core(acc, sb, tid, g_vthi + aoff, g_vtlo + aoff, SS,
               g_wh + boff, g_wl + boff, SS, 2*(st + 1));

    int b = bh >> 4, h = bh & 15;
    int r0w = lane >> 2, cc = (lane & 3) * 2;
    const float* rsvp = g_rsv + (size_t)bh*SS;
    #pragma unroll
    for (int i = 0; i < 2; i++) {
        int d0 = wm*32 + i*16 + r0w;
        size_t rowA = ((size_t)b*DD + h*HD + d0)*SS;
        size_t rowB = rowA + (size_t)8*SS;
        #pragma unroll
        for (int j = 0; j < 8; j++) {
            int s_col = st*128 + wn*64 + j*8 + cc;
            float r0 = rsvp[s_col], r1 = rsvp[s_col + 1];
            __nv_bfloat16 h0,l0,h1,l1;
            splitbf(acc[i][j][0]*r0, h0, l0);
            splitbf(acc[i][j][1]*r1, h1, l1);
            *(unsigned*)(g_Ahi + rowA + s_col) = pack2(h0, h1);
            *(unsigned*)(g_Alo + rowA + s_col) = pack2(l0, l1);
            splitbf(acc[i][j][2]*r0, h0, l0);
            splitbf(acc[i][j][3]*r1, h1, l1);
            *(unsigned*)(g_Ahi + rowB + s_col) = pack2(h0, h1);
            *(unsigned*)(g_Alo + rowB + s_col) = pack2(l0, l1);
        }
    }
}

// ---------------------------------------------------------------------------
// Kernel 6: proj GEMM (3-stage pipeline), per-batch. grid (16, 16)
// ---------------------------------------------------------------------------
#define PJ_STAGE 32768
#define PJ_SMEM  (3*PJ_STAGE)

__global__ __launch_bounds__(256) void proj_mma_kernel(
    const float* __restrict__ bo, float* __restrict__ out, int b)
{
    extern __shared__ char psm[];
    uint32_t sb = smem_u32(psm);

    int tid = threadIdx.x, lane = tid & 31, wid = tid >> 5;
    int wm = wid & 3, wn = wid >> 2;
    int nt = blockIdx.x, mt = blockIdx.y;

    const __nv_bfloat16* Abase   = g_Ahi + ((size_t)b*DD + mt*128)*SS;
    const __nv_bfloat16* AbaseLo = g_Alo + ((size_t)b*DD + mt*128)*SS;
    const __nv_bfloat16* Wbase   = g_Whi + (size_t)(nt*128)*SS;
    const __nv_bfloat16* WbaseLo = g_Wlo + (size_t)(nt*128)*SS;

    int lrow = tid >> 3, lc16 = tid & 7;

    float acc[2][8][4];
    #pragma unroll
    for (int i = 0; i < 2; i++)
        #pragma unroll
        for (int j = 0; j < 8; j++)
            #pragma unroll
            for (int q = 0; q < 4; q++) acc[i][j][q] = 0.f;

    int rowa_l = wm*32 + (lane & 15);
    int ca_l   = (lane >> 4);
    int rowb_l = wn*64 + (lane & 7) + ((lane >> 4) << 3);
    int cb_l   = (lane >> 3) & 1;

    const int NC = 96;

    auto load_chunk = [&](int c, int stg) {
        int seg = c >> 5, kk = (c & 31) * 64;
        const __nv_bfloat16* As = (seg == 1 ? AbaseLo : Abase);
        const __nv_bfloat16* Bs = (seg == 2 ? WbaseLo : Wbase);
        uint32_t sa = sb + stg*PJ_STAGE, sbB = sa + 16384;
        #pragma unroll
        for (int rep = 0; rep < 4; rep++) {
            int row = lrow + rep*32;
            uint32_t off = (uint32_t)row*128 + 16u*(uint32_t)(lc16 ^ (row & 7));
            cpa16(sa  + off, As + (size_t)row*SS + kk + lc16*8);
            cpa16(sbB + off, Bs + (size_t)row*SS + kk + lc16*8);
        }
        asm volatile("cp.async.commit_group;");
    };

    load_chunk(0, 0);
    load_chunk(1, 1);

    for (int c = 0; c < NC; c++) {
        int st = c % 3;
        if (c + 2 < NC) {
            load_chunk(c + 2, (c + 2) % 3);
            asm volatile("cp.async.wait_group 2;");
        } else if (c + 1 < NC) {
            asm volatile("cp.async.wait_group 1;");
        } else {
            asm volatile("cp.async.wait_group 0;");
        }
        __syncthreads();

        uint32_t sa = sb + st*PJ_STAGE, sbB = sa + 16384;
        #pragma unroll
        for (int kstep = 0; kstep < 4; kstep++) {
            uint32_t afr[2][4];
            #pragma unroll
            for (int i = 0; i < 2; i++) {
                int row = rowa_l + i*16;
                int c16 = kstep*2 + ca_l;
                ldsm4(afr[i], sa + (uint32_t)row*128 + 16u*(uint32_t)(c16 ^ (row & 7)));
            }
            uint32_t bfr[4][4];
            #pragma unroll
            for (int j4 = 0; j4 < 4; j4++) {
                int row = rowb_l + j4*16;
                int c16 = kstep*2 + cb_l;
                ldsm4(bfr[j4], sbB + (uint32_t)row*128 + 16u*(uint32_t)(c16 ^ (row & 7)));
            }
            #pragma unroll
            for (int i = 0; i < 2; i++)
                #pragma unroll
                for (int j4 = 0; j4 < 4; j4++) {
                    mma16816(acc[i][2*j4+0], afr[i], bfr[j4][0], bfr[j4][1]);
                    mma16816(acc[i][2*j4+1], afr[i], bfr[j4][2], bfr[j4][3]);
                }
        }
        __syncthreads();
    }

    int r0w = lane >> 2, cc = (lane & 3) * 2;
    const float* bop = bo + nt*128 + wn*64;
    #pragma unroll
    for (int i = 0; i < 2; i++) {
        int m = mt*128 + wm*32 + i*16 + r0w;
        float* row0 = out + ((size_t)b*DD + m)*DD + nt*128 + wn*64;
        float* row1 = row0 + (size_t)8*DD;
        #pragma unroll
        for (int j = 0; j < 8; j++) {
            float2 bb = *(const float2*)(bop + j*8 + cc);
            float2 v0 = make_float2(acc[i][j][0] + bb.x, acc[i][j][1] + bb.y);
            float2 v1 = make_float2(acc[i][j][2] + bb.x, acc[i][j][3] + bb.y);
            *(float2*)(row0 + j*8 + cc) = v0;
            *(float2*)(row1 + j*8 + cc) = v1;
        }
    }
}

// ---------------------------------------------------------------------------
// Host: 2-stream pipeline over batch b (static resources created pre-capture)
// ---------------------------------------------------------------------------
static cudaStream_t g_s1 = nullptr;
static cudaEvent_t  g_evS = nullptr, g_evF = nullptr, g_evW = nullptr, g_evJ = nullptr;
namespace {
struct StreamInit {
    StreamInit() {
        cudaStreamCreateWithFlags(&g_s1, cudaStreamNonBlocking);
        cudaEventCreateWithFlags(&g_evS, cudaEventDisableTiming);
        cudaEventCreateWithFlags(&g_evF, cudaEventDisableTiming);
        cudaEventCreateWithFlags(&g_evW, cudaEventDisableTiming);
        cudaEventCreateWithFlags(&g_evJ, cudaEventDisableTiming);
    }
};
static StreamInit g_stream_init;
}

extern "C" void kernel_launch(void* const* d_in, const int* in_sizes, int n_in,
                              void* d_out, int out_size)
{
    const float* x  = (const float*)d_in[0];
    const float* Wq = (const float*)d_in[2];
    const float* Wk = (const float*)d_in[3];
    const float* Wv = (const float*)d_in[4];
    const float* bq = (const float*)d_in[5];
    const float* bk = (const float*)d_in[6];
    const float* bv = (const float*)d_in[7];
    const float* Wo = (const float*)d_in[8];
    const float* bo = (const float*)d_in[9];
    float* out = (float*)d_out;

    if (!g_s1) {
        cudaStreamCreateWithFlags(&g_s1, cudaStreamNonBlocking);
        cudaEventCreateWithFlags(&g_evS, cudaEventDisableTiming);
        cudaEventCreateWithFlags(&g_evF, cudaEventDisableTiming);
        cudaEventCreateWithFlags(&g_evW, cudaEventDisableTiming);
        cudaEventCreateWithFlags(&g_evJ, cudaEventDisableTiming);
    }

    cudaFuncSetAttribute(qkv_mma_kernel,    cudaFuncAttributeMaxDynamicSharedMemorySize, G3_SMEM);
    cudaFuncSetAttribute(score_gemm_kernel, cudaFuncAttributeMaxDynamicSharedMemorySize, G3_SMEM);
    cudaFuncSetAttribute(av_gemm_kernel,    cudaFuncAttributeMaxDynamicSharedMemorySize, G3_SMEM);
    cudaFuncSetAttribute(proj_mma_kernel,   cudaFuncAttributeMaxDynamicSharedMemorySize, PJ_SMEM);

    // prologue: split(x, Wo) on stream 0, splitw(Wq/Wk/Wv) concurrently on g_s1
    cudaEventRecord(g_evS, 0);
    cudaStreamWaitEvent(g_s1, g_evS, 0);
    split_kernel<<<dim3(DD + BB*SS), 256>>>(Wo, x);
    cudaEventRecord(g_evF, 0);
    splitw_kernel<<<dim3(768), 256, 0, g_s1>>>(Wq, Wk, Wv);
    cudaEventRecord(g_evW, g_s1);
    cudaStreamWaitEvent(0, g_evW, 0);       // stream 0 needs splitw
    cudaStreamWaitEvent(g_s1, g_evF, 0);    // g_s1 needs split

    // per-batch chains: b=0 on capture stream, b=1 on g_s1
    for (int b = 0; b < BB; b++) {
        cudaStream_t strm = (b == 0) ? (cudaStream_t)0 : g_s1;
        qkv_mma_kernel<<<dim3(16, HH, 3), 256, G3_SMEM, strm>>>(bq, bk, bv, b*16);
        score_gemm_kernel<<<dim3(136, HH), 256, G3_SMEM, strm>>>(b*HH);
        select_kernel<<<dim3(SS/16, HH), 512, 0, strm>>>(b*HH);
        av_gemm_kernel<<<dim3(16, HH), 256, G3_SMEM, strm>>>(b*HH);
        proj_mma_kernel<<<dim3(16, 16), 256, PJ_SMEM, strm>>>(bo, out, b);
    }

    cudaEventRecord(g_evJ, g_s1);
    cudaStreamWaitEvent(0, g_evJ, 0);
}

// round 17
// speedup vs baseline: 1.0871x; 1.0003x over previous
#include <cuda_runtime.h>
#include <cuda_bf16.h>
#include <cstdint>
#include <math.h>

#define BB 2
#define HH 16
#define SS 2048
#define HD 128
#define DD 2048
#define KKEEP 819
#define NEGV -1e9f
#define FULLW 0xffffffffu

// ---------------- scratch (device globals; no allocation allowed) ----------
__device__ __nv_bfloat16 g_qhi [BB*HH*SS*HD];  // [bh][s][d]
__device__ __nv_bfloat16 g_qlo [BB*HH*SS*HD];
__device__ __nv_bfloat16 g_khi [BB*HH*SS*HD];  // [bh][t][d]
__device__ __nv_bfloat16 g_klo [BB*HH*SS*HD];
__device__ __nv_bfloat16 g_vthi[BB*HH*HD*SS];  // [bh][d][t]
__device__ __nv_bfloat16 g_vtlo[BB*HH*HD*SS];

__device__ __nv_bfloat16 g_xhi[(size_t)BB*SS*DD];   // x split [b][s][D]
__device__ __nv_bfloat16 g_xlo[(size_t)BB*SS*DD];
__device__ __nv_bfloat16 g_wwhi[3*HH*HD*HD];        // Wq/Wk/Wv split [w][h][e][k]
__device__ __nv_bfloat16 g_wwlo[3*HH*HD*HD];

__device__ float         g_sc [(size_t)BB*HH*SS*SS];   // scores [bh][s][t]
__device__ __nv_bfloat16 g_wh [(size_t)BB*HH*SS*SS];   // UNNORMALIZED weights hi
__device__ __nv_bfloat16 g_wl [(size_t)BB*HH*SS*SS];   // UNNORMALIZED weights lo
__device__ float         g_rsv[(size_t)BB*HH*SS];      // per-row 1/sum

// proj operands (A written directly by av_gemm epilogue)
__device__ __nv_bfloat16 g_Ahi[(size_t)BB*DD*SS];      // [b][i][s]
__device__ __nv_bfloat16 g_Alo[(size_t)BB*DD*SS];
__device__ __nv_bfloat16 g_Whi[(size_t)DD*SS];
__device__ __nv_bfloat16 g_Wlo[(size_t)DD*SS];

// ---------------- common helpers -------------------------------------------
__device__ __forceinline__ uint32_t smem_u32(const void* p) {
    uint32_t a;
    asm("{ .reg .u64 t; cvta.to.shared.u64 t, %1; cvt.u32.u64 %0, t; }" : "=r"(a) : "l"(p));
    return a;
}
__device__ __forceinline__ void cpa16(uint32_t s, const void* g) {
    asm volatile("cp.async.cg.shared.global [%0], [%1], 16;" :: "r"(s), "l"(g));
}
__device__ __forceinline__ void ldsm4(uint32_t* r, uint32_t a) {
    asm volatile("ldmatrix.sync.aligned.m8n8.x4.shared.b16 {%0,%1,%2,%3}, [%4];"
                 : "=r"(r[0]), "=r"(r[1]), "=r"(r[2]), "=r"(r[3]) : "r"(a));
}
__device__ __forceinline__ void mma16816(float* c, const uint32_t* a, uint32_t b0, uint32_t b1) {
    asm volatile("mma.sync.aligned.m16n8k16.row.col.f32.bf16.bf16.f32 "
                 "{%0,%1,%2,%3}, {%4,%5,%6,%7}, {%8,%9}, {%0,%1,%2,%3};"
                 : "+f"(c[0]), "+f"(c[1]), "+f"(c[2]), "+f"(c[3])
                 : "r"(a[0]), "r"(a[1]), "r"(a[2]), "r"(a[3]), "r"(b0), "r"(b1));
}
__device__ __forceinline__ void splitbf(float a, __nv_bfloat16& h, __nv_bfloat16& l) {
    h = __float2bfloat16(a);
    l = __float2bfloat16(a - __bfloat162float(h));
}
__device__ __forceinline__ unsigned pack2(__nv_bfloat16 a, __nv_bfloat16 b) {
    return (unsigned)*(unsigned short*)&a | ((unsigned)*(unsigned short*)&b << 16);
}

// ---------------------------------------------------------------------------
// Segmented GEMM core: 128x128 tile, 3 hi/lo term-segments along K,
// 2 smem buffers per stage (A,B; 32KB), 3-stage cp.async pipeline.
// D += A0·B0^T + A1·B1^T + A2·B2^T, each segment ncps 64-wide K-chunks.
// ---------------------------------------------------------------------------
#define SEG_STAGE 32768
#define SEG_SMEM  (3*SEG_STAGE)

__device__ __forceinline__ void gemm_seg(
    float (*acc)[8][4], uint32_t sb, int tid,
    const __nv_bfloat16* A0, const __nv_bfloat16* A1, const __nv_bfloat16* A2,
    size_t strideA,
    const __nv_bfloat16* B0, const __nv_bfloat16* B1, const __nv_bfloat16* B2,
    size_t strideB,
    int ncps)   // 64-wide K-chunks PER SEGMENT; NC = 3*ncps
{
    int lane = tid & 31, wid = tid >> 5;
    int wm = wid & 3, wn = wid >> 2;
    int lrow = tid >> 3, lc16 = tid & 7;

    int rowa_l = wm*32 + (lane & 15);
    int ca_l   = (lane >> 4);
    int rowb_l = wn*64 + (lane & 7) + ((lane >> 4) << 3);
    int cb_l   = (lane >> 3) & 1;

    const int NC = 3*ncps;

    auto load_chunk = [&](int c, int stg) {
        int seg = c / ncps, kk = (c - seg*ncps) * 64;
        const __nv_bfloat16* As = (seg == 0 ? A0 : seg == 1 ? A1 : A2);
        const __nv_bfloat16* Bs = (seg == 0 ? B0 : seg == 1 ? B1 : B2);
        uint32_t sa = sb + stg*SEG_STAGE, sbB = sa + 16384;
        #pragma unroll
        for (int rep = 0; rep < 4; rep++) {
            int row = lrow + rep*32;
            uint32_t off = (uint32_t)row*128 + 16u*(uint32_t)(lc16 ^ (row & 7));
            cpa16(sa  + off, As + (size_t)row*strideA + kk + lc16*8);
            cpa16(sbB + off, Bs + (size_t)row*strideB + kk + lc16*8);
        }
        asm volatile("cp.async.commit_group;");
    };

    load_chunk(0, 0);
    if (NC > 1) load_chunk(1, 1);

    for (int c = 0; c < NC; c++) {
        int st = c % 3;
        if (c + 2 < NC) {
            load_chunk(c + 2, (c + 2) % 3);
            asm volatile("cp.async.wait_group 2;");
        } else if (c + 1 < NC) {
            asm volatile("cp.async.wait_group 1;");
        } else {
            asm volatile("cp.async.wait_group 0;");
        }
        __syncthreads();

        uint32_t sa = sb + st*SEG_STAGE, sbB = sa + 16384;
        #pragma unroll
        for (int kstep = 0; kstep < 4; kstep++) {
            uint32_t afr[2][4];
            #pragma unroll
            for (int i = 0; i < 2; i++) {
                int row = rowa_l + i*16;
                int c16 = kstep*2 + ca_l;
                ldsm4(afr[i], sa + (uint32_t)row*128 + 16u*(uint32_t)(c16 ^ (row & 7)));
            }
            uint32_t bfr[4][4];
            #pragma unroll
            for (int j4 = 0; j4 < 4; j4++) {
                int row = rowb_l + j4*16;
                int c16 = kstep*2 + cb_l;
                ldsm4(bfr[j4], sbB + (uint32_t)row*128 + 16u*(uint32_t)(c16 ^ (row & 7)));
            }
            #pragma unroll
            for (int i = 0; i < 2; i++)
                #pragma unroll
                for (int j4 = 0; j4 < 4; j4++) {
                    mma16816(acc[i][2*j4+0], afr[i], bfr[j4][0], bfr[j4][1]);
                    mma16816(acc[i][2*j4+1], afr[i], bfr[j4][2], bfr[j4][3]);
                }
        }
        __syncthreads();
    }
}

// ---------------------------------------------------------------------------
// Kernel 1a: fp32 -> bf16 hi/lo split for Wo + x (rows of 2048)
// ---------------------------------------------------------------------------
__global__ __launch_bounds__(256) void split_kernel(
    const float* __restrict__ Wo, const float* __restrict__ x)
{
    int row = blockIdx.x;
    int tid = threadIdx.x;
    const float* src;
    __nv_bfloat16 *dhi, *dlo;
    if (row < DD) {
        src = Wo + (size_t)row*SS;
        dhi = g_Whi + (size_t)row*SS; dlo = g_Wlo + (size_t)row*SS;
    } else {
        int r = row - DD;
        src = x + (size_t)r*DD;
        dhi = g_xhi + (size_t)r*DD; dlo = g_xlo + (size_t)r*DD;
    }

    int base = tid * 8;
    float4 f0 = *(const float4*)(src + base);
    float4 f1 = *(const float4*)(src + base + 4);
    float v[8] = {f0.x, f0.y, f0.z, f0.w, f1.x, f1.y, f1.z, f1.w};
    unsigned hw[4], lw[4];
    #pragma unroll
    for (int p = 0; p < 4; p++) {
        __nv_bfloat16 ha, hb, la, lb;
        splitbf(v[2*p], ha, la);
        splitbf(v[2*p+1], hb, lb);
        hw[p] = pack2(ha, hb);
        lw[p] = pack2(la, lb);
    }
    *(uint4*)(dhi + base) = make_uint4(hw[0], hw[1], hw[2], hw[3]);
    *(uint4*)(dlo + base) = make_uint4(lw[0], lw[1], lw[2], lw[3]);
}

// ---------------------------------------------------------------------------
// Kernel 1b: fp32 -> bf16 hi/lo split for Wq/Wk/Wv (flat, 4 elems/thread)
// ---------------------------------------------------------------------------
__global__ __launch_bounds__(256) void splitw_kernel(
    const float* __restrict__ Wq, const float* __restrict__ Wk,
    const float* __restrict__ Wv)
{
    int base = (blockIdx.x*256 + threadIdx.x) * 4;
    int wsel = base >> 18;
    int off  = base & 262143;
    const float* src = (wsel == 0 ? Wq : wsel == 1 ? Wk : Wv) + off;
    float4 f = *(const float4*)src;
    __nv_bfloat16 h0,l0,h1,l1,h2,l2,h3,l3;
    splitbf(f.x,h0,l0); splitbf(f.y,h1,l1); splitbf(f.z,h2,l2); splitbf(f.w,h3,l3);
    *(uint2*)(g_wwhi + base) = make_uint2(pack2(h0,h1), pack2(h2,h3));
    *(uint2*)(g_wwlo + base) = make_uint2(pack2(l0,l1), pack2(l2,l3));
}

// ---------------------------------------------------------------------------
// Kernel 2: QKV projections via segmented HMMA. grid (16, HH, 3) + mt_base
// ---------------------------------------------------------------------------
__global__ __launch_bounds__(256) void qkv_mma_kernel(
    const float* __restrict__ bq, const float* __restrict__ bk,
    const float* __restrict__ bv, int mt_base)
{
    int mt = mt_base + blockIdx.x, h = blockIdx.y, w = blockIdx.z;
    extern __shared__ char sm3[];
    uint32_t sb = smem_u32(sm3);
    int tid = threadIdx.x, lane = tid & 31, wid = tid >> 5;
    int wm = wid & 3, wn = wid >> 2;

    float acc[2][8][4];
    #pragma unroll
    for (int i = 0; i < 2; i++)
        #pragma unroll
        for (int j = 0; j < 8; j++)
            #pragma unroll
            for (int q = 0; q < 4; q++) acc[i][j][q] = 0.f;

    const __nv_bfloat16* Ah = g_xhi + (size_t)(mt*128)*DD + h*HD;
    const __nv_bfloat16* Al = g_xlo + (size_t)(mt*128)*DD + h*HD;
    const __nv_bfloat16* Bh = g_wwhi + (size_t)((w*HH + h)*HD)*HD;
    const __nv_bfloat16* Bl = g_wwlo + (size_t)((w*HH + h)*HD)*HD;
    gemm_seg(acc, sb, tid, Ah, Al, Ah, DD, Bh, Bh, Bl, HD, 2);

    const float* bias = (w == 0 ? bq : w == 1 ? bk : bv) + h*HD;
    int b = mt >> 4;
    int bh = b*HH + h;
    int sbase = (mt*128) & (SS - 1);
    int r0w = lane >> 2, cc = (lane & 3)*2;

    if (w < 2) {
        __nv_bfloat16* dh = (w == 0 ? g_qhi : g_khi);
        __nv_bfloat16* dl = (w == 0 ? g_qlo : g_klo);
        #pragma unroll
        for (int i = 0; i < 2; i++) {
            int m0 = wm*32 + i*16 + r0w;
            size_t row0 = ((size_t)bh*SS + sbase + m0)*HD;
            size_t row1 = row0 + (size_t)8*HD;
            #pragma unroll
            for (int j = 0; j < 8; j++) {
                int d0 = wn*64 + j*8 + cc;
                float b0 = bias[d0], b1 = bias[d0+1];
                __nv_bfloat16 ha,la,hb,lb;
                splitbf(acc[i][j][0] + b0, ha, la);
                splitbf(acc[i][j][1] + b1, hb, lb);
                *(unsigned*)(dh + row0 + d0) = pack2(ha, hb);
                *(unsigned*)(dl + row0 + d0) = pack2(la, lb);
                splitbf(acc[i][j][2] + b0, ha, la);
                splitbf(acc[i][j][3] + b1, hb, lb);
                *(unsigned*)(dh + row1 + d0) = pack2(ha, hb);
                *(unsigned*)(dl + row1 + d0) = pack2(la, lb);
            }
        }
    } else {
        __nv_bfloat16* th = (__nv_bfloat16*)sm3;          // [d][m] 128x128
        __nv_bfloat16* tl = th + 128*128;
        __syncthreads();
        #pragma unroll
        for (int i = 0; i < 2; i++) {
            int m0 = wm*32 + i*16 + r0w;
            #pragma unroll
            for (int j = 0; j < 8; j++) {
                int d0 = wn*64 + j*8 + cc;
                float b0 = bias[d0], b1 = bias[d0+1];
                __nv_bfloat16 hh, ll;
                splitbf(acc[i][j][0] + b0, hh, ll);
                th[d0*128 + m0] = hh;         tl[d0*128 + m0] = ll;
                splitbf(acc[i][j][1] + b1, hh, ll);
                th[(d0+1)*128 + m0] = hh;     tl[(d0+1)*128 + m0] = ll;
                splitbf(acc[i][j][2] + b0, hh, ll);
                th[d0*128 + m0 + 8] = hh;     tl[d0*128 + m0 + 8] = ll;
                splitbf(acc[i][j][3] + b1, hh, ll);
                th[(d0+1)*128 + m0 + 8] = hh; tl[(d0+1)*128 + m0 + 8] = ll;
            }
        }
        __syncthreads();
        int d = tid >> 1, half = tid & 1;
        size_t go = ((size_t)bh*HD + d)*SS + sbase + half*64;
        const uint4* s4h = (const uint4*)(th + d*128 + half*64);
        const uint4* s4l = (const uint4*)(tl + d*128 + half*64);
        #pragma unroll
        for (int p = 0; p < 8; p++) {
            *(uint4*)(g_vthi + go + p*8) = s4h[p];
            *(uint4*)(g_vtlo + go + p*8) = s4l[p];
        }
    }
}

// ---------------------------------------------------------------------------
// Kernel 3: score GEMM (segmented). Triangular grid (136, HH) + bh_base
// ---------------------------------------------------------------------------
__global__ __launch_bounds__(256) void score_gemm_kernel(int bh_base)
{
    int l = blockIdx.x;
    int it = 0, tbase = 0;
    while (l >= tbase + it + 1) { tbase += it + 1; it++; }
    int jt = l - tbase;
    int bh = bh_base + blockIdx.y;

    extern __shared__ char sm3[];
    uint32_t sb = smem_u32(sm3);
    int tid = threadIdx.x, lane = tid & 31, wid = tid >> 5;
    int wm = wid & 3, wn = wid >> 2;

    float acc[2][8][4];
    #pragma unroll
    for (int i = 0; i < 2; i++)
        #pragma unroll
        for (int j = 0; j < 8; j++)
            #pragma unroll
            for (int q = 0; q < 4; q++) acc[i][j][q] = 0.f;

    const __nv_bfloat16* Ah = g_qhi + ((size_t)bh*SS + it*128)*HD;
    const __nv_bfloat16* Al = g_qlo + ((size_t)bh*SS + it*128)*HD;
    const __nv_bfloat16* Bh = g_khi + ((size_t)bh*SS + jt*128)*HD;
    const __nv_bfloat16* Bl = g_klo + ((size_t)bh*SS + jt*128)*HD;
    gemm_seg(acc, sb, tid, Ah, Al, Ah, HD, Bh, Bh, Bl, HD, 2);

    const float scale = 0.08838834764831845f;
    int r0w = lane >> 2, cc = (lane & 3) * 2;
    #pragma unroll
    for (int i = 0; i < 2; i++) {
        int m0 = it*128 + wm*32 + i*16 + r0w;
        int m1 = m0 + 8;
        float* row0 = g_sc + ((size_t)bh*SS + m0)*SS + jt*128 + wn*64;
        float* row1 = row0 + (size_t)8*SS;
        #pragma unroll
        for (int j = 0; j < 8; j++) {
            int j0 = jt*128 + wn*64 + j*8 + cc;
            float2 v0, v1;
            v0.x = (j0     <= m0) ? acc[i][j][0]*scale : NEGV;
            v0.y = (j0 + 1 <= m0) ? acc[i][j][1]*scale : NEGV;
            v1.x = (j0     <= m1) ? acc[i][j][2]*scale : NEGV;
            v1.y = (j0 + 1 <= m1) ? acc[i][j][3]*scale : NEGV;
            *(float2*)(row0 + j*8 + cc) = v0;
            *(float2*)(row1 + j*8 + cc) = v1;
        }
    }
}

// ---------------------------------------------------------------------------
// Kernel 4: exact top-k select (early-exit radix) + fused exp/sum
// ---------------------------------------------------------------------------
__device__ __forceinline__ unsigned f2key(float f) {
    unsigned u = __float_as_uint(f);
    return u ^ ((u & 0x80000000u) ? 0xFFFFFFFFu : 0x80000000u);
}
__device__ __forceinline__ float key2f(unsigned k) {
    unsigned u = (k & 0x80000000u) ? (k ^ 0x80000000u) : ~k;
    return __uint_as_float(u);
}

__global__ __launch_bounds__(512) void select_kernel(int bh_base)
{
    __shared__ int hist[16*256];

    int bh   = bh_base + blockIdx.y;
    int s0   = (gridDim.x - 1 - blockIdx.x) * 16;
    int tid  = threadIdx.x;
    int lane = tid & 31, wid = tid >> 5;
    int s    = s0 + wid;
    int nvalid = s + 1;
    int nround = (nvalid + 31) & ~31;

    const float* row = g_sc + ((size_t)bh*SS + s)*SS;
    int* hh = hist + wid*256;

    float lm  = -3.4e38f;
    float thr = -3.4e38f;

    if (s >= KKEEP - 1) {
        unsigned prefix = 0; int K = KKEEP;
        for (int pass = 0; pass < 4; pass++) {
            int shift = 24 - pass*8;
            #pragma unroll
            for (int i = lane; i < 256; i += 32) hh[i] = 0;
            __syncwarp();
            for (int t = lane; t < nround; t += 32) {
                bool valid = (t < nvalid);
                float v = valid ? row[t] : NEGV;
                if (pass == 0 && valid) lm = fmaxf(lm, v);
                unsigned key = f2key(v);
                bool cand = valid &&
                    ((pass == 0) || (((key ^ prefix) >> (shift + 8)) == 0u));
                int bin = cand ? (int)((key >> shift) & 255u) : -1;
                unsigned peers = __match_any_sync(FULLW, bin);
                if (cand && lane == (__ffs(peers) - 1))
                    atomicAdd(&hh[bin], __popc(peers));
            }
            __syncwarp();
            int hv[8]; int ssum = 0;
            #pragma unroll
            for (int i = 0; i < 8; i++) { hv[i] = hh[lane*8 + i]; ssum += hv[i]; }
            int suf = ssum;
            #pragma unroll
            for (int off = 1; off < 32; off <<= 1) {
                int v = __shfl_down_sync(FULLW, suf, off);
                if (lane + off < 32) suf += v;
            }
            int above = suf - ssum;
            int selbin = -1, newK = 0, cnt = 0;
            if (suf >= K && above < K) {
                int run = above;
                #pragma unroll
                for (int bb2 = 7; bb2 >= 0; bb2--) {
                    run += hv[bb2];
                    if (run >= K) {
                        selbin = lane*8 + bb2;
                        newK = K - (run - hv[bb2]);
                        cnt = hv[bb2];
                        break;
                    }
                }
            }
            unsigned msk = __ballot_sync(FULLW, selbin >= 0);
            int src = __ffs(msk) - 1;
            selbin = __shfl_sync(FULLW, selbin, src);
            newK   = __shfl_sync(FULLW, newK,  src);
            cnt    = __shfl_sync(FULLW, cnt,   src);
            prefix |= ((unsigned)selbin) << shift;
            K = newK;
            if (newK == cnt) break;   // whole bin kept -> bin floor is valid thr
        }
        thr = key2f(prefix);
    } else {
        for (int t = lane; t < nvalid; t += 32) lm = fmaxf(lm, row[t]);
    }

    #pragma unroll
    for (int off = 16; off > 0; off >>= 1)
        lm = fmaxf(lm, __shfl_xor_sync(FULLW, lm, off));

    int CEIL = (s0 & ~127) + 128;
    size_t go = ((size_t)bh*SS + s)*SS;
    float ls = 0.f;
    for (int t4 = lane*4; t4 < CEIL; t4 += 128) {
        float w0 = 0.f, w1 = 0.f, w2 = 0.f, w3 = 0.f;
        if (t4 + 3 < nvalid) {
            float4 v4 = *(const float4*)(row + t4);
            if (v4.x >= thr) w0 = __expf(v4.x - lm);
            if (v4.y >= thr) w1 = __expf(v4.y - lm);
            if (v4.z >= thr) w2 = __expf(v4.z - lm);
            if (v4.w >= thr) w3 = __expf(v4.w - lm);
        } else if (t4 < nvalid) {
            float vv;
            vv = row[t4];
            if (vv >= thr) w0 = __expf(vv - lm);
            if (t4 + 1 < nvalid) { vv = row[t4+1]; if (vv >= thr) w1 = __expf(vv - lm); }
            if (t4 + 2 < nvalid) { vv = row[t4+2]; if (vv >= thr) w2 = __expf(vv - lm); }
        }
        ls += (w0 + w1) + (w2 + w3);
        __nv_bfloat16 h0,l0,h1,l1,h2,l2,h3,l3;
        splitbf(w0,h0,l0); splitbf(w1,h1,l1);
        splitbf(w2,h2,l2); splitbf(w3,h3,l3);
        *(uint2*)(g_wh + go + t4) = make_uint2(pack2(h0,h1), pack2(h2,h3));
        *(uint2*)(g_wl + go + t4) = make_uint2(pack2(l0,l1), pack2(l2,l3));
    }
    #pragma unroll
    for (int off = 16; off > 0; off >>= 1)
        ls += __shfl_xor_sync(FULLW, ls, off);
    if (lane == 0) g_rsv[(size_t)bh*SS + s] = 1.f / ls;
}

// ---------------------------------------------------------------------------
// Kernel 5: AV GEMM (segmented): outT[d, s] = rsv[s]*sum_t V^T[d,t]*W[s,t]
// ---------------------------------------------------------------------------
__global__ __launch_bounds__(256) void av_gemm_kernel(int bh_base)
{
    int st = gridDim.x - 1 - blockIdx.x;
    int bh = bh_base + blockIdx.y;

    extern __shared__ char sm3[];
    uint32_t sb = smem_u32(sm3);
    int tid = threadIdx.x, lane = tid & 31, wid = tid >> 5;
    int wm = wid & 3, wn = wid >> 2;

    float acc[2][8][4];
    #pragma unroll
    for (int i = 0; i < 2; i++)
        #pragma unroll
        for (int j = 0; j < 8; j++)
            #pragma unroll
            for (int q = 0; q < 4; q++) acc[i][j][q] = 0.f;

    const __nv_bfloat16* Ah = g_vthi + (size_t)bh*HD*SS;
    const __nv_bfloat16* Al = g_vtlo + (size_t)bh*HD*SS;
    const __nv_bfloat16* Bh = g_wh + ((size_t)bh*SS + st*128)*SS;
    const __nv_bfloat16* Bl = g_wl + ((size_t)bh*SS + st*128)*SS;
    gemm_seg(acc, sb, tid, Ah, Al, Ah, SS, Bh, Bh, Bl, SS, 2*(st + 1));

    int b = bh >> 4, h = bh & 15;
    int r0w = lane >> 2, cc = (lane & 3) * 2;
    const float* rsvp = g_rsv + (size_t)bh*SS;
    #pragma unroll
    for (int i = 0; i < 2; i++) {
        int d0 = wm*32 + i*16 + r0w;
        size_t rowA = ((size_t)b*DD + h*HD + d0)*SS;
        size_t rowB = rowA + (size_t)8*SS;
        #pragma unroll
        for (int j = 0; j < 8; j++) {
            int s_col = st*128 + wn*64 + j*8 + cc;
            float r0 = rsvp[s_col], r1 = rsvp[s_col + 1];
            __nv_bfloat16 h0,l0,h1,l1;
            splitbf(acc[i][j][0]*r0, h0, l0);
            splitbf(acc[i][j][1]*r1, h1, l1);
            *(unsigned*)(g_Ahi + rowA + s_col) = pack2(h0, h1);
            *(unsigned*)(g_Alo + rowA + s_col) = pack2(l0, l1);
            splitbf(acc[i][j][2]*r0, h0, l0);
            splitbf(acc[i][j][3]*r1, h1, l1);
            *(unsigned*)(g_Ahi + rowB + s_col) = pack2(h0, h1);
            *(unsigned*)(g_Alo + rowB + s_col) = pack2(l0, l1);
        }
    }
}

// ---------------------------------------------------------------------------
// Kernel 6: proj GEMM (segmented), per-batch. grid (16, 16)
// ---------------------------------------------------------------------------
__global__ __launch_bounds__(256) void proj_mma_kernel(
    const float* __restrict__ bo, float* __restrict__ out, int b)
{
    extern __shared__ char psm[];
    uint32_t sb = smem_u32(psm);

    int tid = threadIdx.x, lane = tid & 31, wid = tid >> 5;
    int wm = wid & 3, wn = wid >> 2;
    int nt = blockIdx.x, mt = blockIdx.y;

    float acc[2][8][4];
    #pragma unroll
    for (int i = 0; i < 2; i++)
        #pragma unroll
        for (int j = 0; j < 8; j++)
            #pragma unroll
            for (int q = 0; q < 4; q++) acc[i][j][q] = 0.f;

    const __nv_bfloat16* Ah = g_Ahi + ((size_t)b*DD + mt*128)*SS;
    const __nv_bfloat16* Al = g_Alo + ((size_t)b*DD + mt*128)*SS;
    const __nv_bfloat16* Bh = g_Whi + (size_t)(nt*128)*SS;
    const __nv_bfloat16* Bl = g_Wlo + (size_t)(nt*128)*SS;
    gemm_seg(acc, sb, tid, Ah, Al, Ah, SS, Bh, Bh, Bl, SS, 32);

    int r0w = lane >> 2, cc = (lane & 3) * 2;
    const float* bop = bo + nt*128 + wn*64;
    #pragma unroll
    for (int i = 0; i < 2; i++) {
        int m = mt*128 + wm*32 + i*16 + r0w;
        float* row0 = out + ((size_t)b*DD + m)*DD + nt*128 + wn*64;
        float* row1 = row0 + (size_t)8*DD;
        #pragma unroll
        for (int j = 0; j < 8; j++) {
            float2 bb = *(const float2*)(bop + j*8 + cc);
            float2 v0 = make_float2(acc[i][j][0] + bb.x, acc[i][j][1] + bb.y);
            float2 v1 = make_float2(acc[i][j][2] + bb.x, acc[i][j][3] + bb.y);
            *(float2*)(row0 + j*8 + cc) = v0;
            *(float2*)(row1 + j*8 + cc) = v1;
        }
    }
}

// ---------------------------------------------------------------------------
// Host: 2-stream pipeline over batch b (static resources created pre-capture)
// ---------------------------------------------------------------------------
static cudaStream_t g_s1 = nullptr;
static cudaEvent_t  g_evS = nullptr, g_evF = nullptr, g_evW = nullptr, g_evJ = nullptr;
namespace {
struct StreamInit {
    StreamInit() {
        cudaStreamCreateWithFlags(&g_s1, cudaStreamNonBlocking);
        cudaEventCreateWithFlags(&g_evS, cudaEventDisableTiming);
        cudaEventCreateWithFlags(&g_evF, cudaEventDisableTiming);
        cudaEventCreateWithFlags(&g_evW, cudaEventDisableTiming);
        cudaEventCreateWithFlags(&g_evJ, cudaEventDisableTiming);
    }
};
static StreamInit g_stream_init;
}

extern "C" void kernel_launch(void* const* d_in, const int* in_sizes, int n_in,
                              void* d_out, int out_size)
{
    const float* x  = (const float*)d_in[0];
    const float* Wq = (const float*)d_in[2];
    const float* Wk = (const float*)d_in[3];
    const float* Wv = (const float*)d_in[4];
    const float* bq = (const float*)d_in[5];
    const float* bk = (const float*)d_in[6];
    const float* bv = (const float*)d_in[7];
    const float* Wo = (const float*)d_in[8];
    const float* bo = (const float*)d_in[9];
    float* out = (float*)d_out;

    if (!g_s1) {
        cudaStreamCreateWithFlags(&g_s1, cudaStreamNonBlocking);
        cudaEventCreateWithFlags(&g_evS, cudaEventDisableTiming);
        cudaEventCreateWithFlags(&g_evF, cudaEventDisableTiming);
        cudaEventCreateWithFlags(&g_evW, cudaEventDisableTiming);
        cudaEventCreateWithFlags(&g_evJ, cudaEventDisableTiming);
    }

    cudaFuncSetAttribute(qkv_mma_kernel,    cudaFuncAttributeMaxDynamicSharedMemorySize, SEG_SMEM);
    cudaFuncSetAttribute(score_gemm_kernel, cudaFuncAttributeMaxDynamicSharedMemorySize, SEG_SMEM);
    cudaFuncSetAttribute(av_gemm_kernel,    cudaFuncAttributeMaxDynamicSharedMemorySize, SEG_SMEM);
    cudaFuncSetAttribute(proj_mma_kernel,   cudaFuncAttributeMaxDynamicSharedMemorySize, SEG_SMEM);

    // prologue: split(x, Wo) on stream 0, splitw(Wq/Wk/Wv) concurrently on g_s1
    cudaEventRecord(g_evS, 0);
    cudaStreamWaitEvent(g_s1, g_evS, 0);
    split_kernel<<<dim3(DD + BB*SS), 256>>>(Wo, x);
    cudaEventRecord(g_evF, 0);
    splitw_kernel<<<dim3(768), 256, 0, g_s1>>>(Wq, Wk, Wv);
    cudaEventRecord(g_evW, g_s1);
    cudaStreamWaitEvent(0, g_evW, 0);       // stream 0 needs splitw
    cudaStreamWaitEvent(g_s1, g_evF, 0);    // g_s1 needs split

    // per-batch chains: b=0 on capture stream, b=1 on g_s1
    for (int b = 0; b < BB; b++) {
        cudaStream_t strm = (b == 0) ? (cudaStream_t)0 : g_s1;
        qkv_mma_kernel<<<dim3(16, HH, 3), 256, SEG_SMEM, strm>>>(bq, bk, bv, b*16);
        score_gemm_kernel<<<dim3(136, HH), 256, SEG_SMEM, strm>>>(b*HH);
        select_kernel<<<dim3(SS/16, HH), 512, 0, strm>>>(b*HH);
        av_gemm_kernel<<<dim3(16, HH), 256, SEG_SMEM, strm>>>(b*HH);
        proj_mma_kernel<<<dim3(16, 16), 256, SEG_SMEM, strm>>>(bo, out, b);
    }

    cudaEventRecord(g_evJ, g_s1);
    cudaStreamWaitEvent(0, g_evJ, 0);
}